// round 11
// baseline (speedup 1.0000x reference)
#include <cuda_runtime.h>
#include <cuda_bf16.h>
#include <cuda_fp16.h>
#include <math.h>
#include <stdint.h>
#include <float.h>

#define B_  2
#define T_  2048
#define HID_ 2048
#define H_  16
#define D_  128
#define BH_ (B_*H_)
#define BT_ (B_*T_)

// ---------------- device scratch ----------------
__device__ float g_ve[BH_ * D_];
__device__ float g_v1535[BH_ * D_];

// bf16 split operands
__device__ __align__(16) __nv_bfloat16 g_Hh[(size_t)BT_ * HID_];
__device__ __align__(16) __nv_bfloat16 g_Hl[(size_t)BT_ * HID_];
__device__ __align__(16) __nv_bfloat16 g_Wh[3][(size_t)HID_ * HID_];
__device__ __align__(16) __nv_bfloat16 g_Wl[3][(size_t)HID_ * HID_];
__device__ __align__(16) __nv_bfloat16 g_OWh[(size_t)HID_ * HID_];
__device__ __align__(16) __nv_bfloat16 g_OWl[(size_t)HID_ * HID_];
__device__ __align__(16) __nv_bfloat16 g_AOh[(size_t)BT_ * HID_];
__device__ __align__(16) __nv_bfloat16 g_AOl[(size_t)BT_ * HID_];
__device__ __align__(16) __nv_bfloat16 g_Qh[(size_t)BH_ * T_ * D_];
__device__ __align__(16) __nv_bfloat16 g_Ql[(size_t)BH_ * T_ * D_];
__device__ __align__(16) __nv_bfloat16 g_Kh[(size_t)BH_ * T_ * D_];
__device__ __align__(16) __nv_bfloat16 g_Kl[(size_t)BH_ * T_ * D_];
// fp16 V transposed: Vt[bh][d][k]
__device__ __align__(16) __half g_Vth[(size_t)BH_ * D_ * T_];

// ---------------- PTX helpers (compute_103-safe) ----------------
__device__ __forceinline__ uint32_t smem_u32(const void* p) {
    uint32_t a;
    asm("{ .reg .u64 t; cvta.to.shared.u64 t, %1; cvt.u32.u64 %0, t; }" : "=r"(a) : "l"(p));
    return a;
}
__device__ __forceinline__ void cp_async16(uint32_t dst, const void* src) {
    asm volatile("cp.async.cg.shared.global [%0], [%1], 16;" :: "r"(dst), "l"(src));
}
#define CP_COMMIT() asm volatile("cp.async.commit_group;" ::: "memory")
#define CP_WAIT(N)  asm volatile("cp.async.wait_group %0;" :: "n"(N) : "memory")

#define LDSM_X4(r, addr) \
    asm volatile("ldmatrix.sync.aligned.m8n8.x4.shared.b16 {%0,%1,%2,%3}, [%4];" \
        : "=r"((r)[0]), "=r"((r)[1]), "=r"((r)[2]), "=r"((r)[3]) : "r"(addr))

__device__ __forceinline__ void mma16816_bf(float* c, const uint32_t* a, const uint32_t* b) {
    asm volatile("mma.sync.aligned.m16n8k16.row.col.f32.bf16.bf16.f32 "
        "{%0,%1,%2,%3}, {%4,%5,%6,%7}, {%8,%9}, {%0,%1,%2,%3};"
        : "+f"(c[0]), "+f"(c[1]), "+f"(c[2]), "+f"(c[3])
        : "r"(a[0]), "r"(a[1]), "r"(a[2]), "r"(a[3]), "r"(b[0]), "r"(b[1]));
}
__device__ __forceinline__ void mma16816_fp(float* c, const uint32_t* a, const uint32_t* b) {
    asm volatile("mma.sync.aligned.m16n8k16.row.col.f32.f16.f16.f32 "
        "{%0,%1,%2,%3}, {%4,%5,%6,%7}, {%8,%9}, {%0,%1,%2,%3};"
        : "+f"(c[0]), "+f"(c[1]), "+f"(c[2]), "+f"(c[3])
        : "r"(a[0]), "r"(a[1]), "r"(a[2]), "r"(a[3]), "r"(b[0]), "r"(b[1]));
}

__device__ __forceinline__ void split2(float x, __nv_bfloat16& h, __nv_bfloat16& l) {
    h = __float2bfloat16(x);
    l = __float2bfloat16(x - __bfloat162float(h));
}
__device__ __forceinline__ uint32_t packh2(float a, float b) {
    __half2 h = __floats2half2_rn(a, b);
    return *reinterpret_cast<uint32_t*>(&h);
}

// ---------------- merged fp32 -> bf16 hi/lo split for inputs ----------------
__global__ void convert_all(const float* __restrict__ hs,
                            const float* __restrict__ qw, const float* __restrict__ kw,
                            const float* __restrict__ vw, const float* __restrict__ ow)
{
    const int sel = blockIdx.y;
    if (sel > 0 && blockIdx.x >= 4096) return;
    const size_t i = ((size_t)blockIdx.x * blockDim.x + threadIdx.x) * 4;
    const float* s;
    __nv_bfloat16 *hi, *lo;
    switch (sel) {
        case 0: s = hs; hi = g_Hh;    lo = g_Hl;    break;
        case 1: s = qw; hi = g_Wh[0]; lo = g_Wl[0]; break;
        case 2: s = kw; hi = g_Wh[1]; lo = g_Wl[1]; break;
        case 3: s = vw; hi = g_Wh[2]; lo = g_Wl[2]; break;
        default: s = ow; hi = g_OWh;  lo = g_OWl;   break;
    }
    const float4 v = *(const float4*)(s + i);
    __nv_bfloat16 h0,h1,h2,h3,l0,l1,l2,l3;
    split2(v.x,h0,l0); split2(v.y,h1,l1); split2(v.z,h2,l2); split2(v.w,h3,l3);
    *(__nv_bfloat162*)(hi + i)     = __nv_bfloat162(h0, h1);
    *(__nv_bfloat162*)(hi + i + 2) = __nv_bfloat162(h2, h3);
    *(__nv_bfloat162*)(lo + i)     = __nv_bfloat162(l0, l1);
    *(__nv_bfloat162*)(lo + i + 2) = __nv_bfloat162(l2, l3);
}

// ---------------- mma.sync split-bf16 GEMM (projections), 3-stage pipeline ----------------
// MODE 1: QKV proj grid(48,32): x=(w*16+n). Q/K: rope fused -> bf16 splits.
//         V: transposed fp16 -> g_Vth + row-1535 fp32 save.
// MODE 0: O proj   grid(16,32) -> C (d_out)
#define GT_TILE  16384
#define GT_STAGE (4 * GT_TILE)     // 64KB per stage (Ah,Al,Bh,Bl)
#define GT_SMEM  (3 * GT_STAGE)    // 192KB, 3 stages

template<int MODE>
__global__ void __launch_bounds__(256) gemm_mma(float* __restrict__ C)
{
    extern __shared__ char smem[];
    const uint32_t sbase = smem_u32(smem);
    const int tid = threadIdx.x;
    const int wid = tid >> 5;
    const int lane = tid & 31;

    int wsel = 0, hsel = 0, mloc, nloc;
    const __nv_bfloat16 *pA0, *pA1, *pB0, *pB1;
    if (MODE == 1) {
        wsel = blockIdx.x >> 4;
        hsel = blockIdx.x & 15;
        mloc = blockIdx.y * 128; nloc = hsel * 128;
        pA0 = g_Hh; pA1 = g_Hl; pB0 = g_Wh[wsel]; pB1 = g_Wl[wsel];
    } else {
        mloc = blockIdx.y * 128; nloc = blockIdx.x * 128;
        pA0 = g_AOh; pA1 = g_AOl; pB0 = g_OWh; pB1 = g_OWl;
    }

    const int part = tid >> 6;
    const int u = tid & 63;
    const __nv_bfloat16* gsrc = (part == 0) ? pA0 : (part == 1) ? pA1 : (part == 2) ? pB0 : pB1;
    const int growbase = (part < 2) ? mloc : nloc;
    const uint32_t tpart = sbase + part * GT_TILE;

    auto load_stage = [&](int c, int s) {
#pragma unroll
        for (int rr = 0; rr < 2; rr++) {
            const int r = u * 2 + rr;
            const __nv_bfloat16* src = gsrc + (size_t)(growbase + r) * 2048 + c * 64;
            const uint32_t drow = tpart + s * GT_STAGE + r * 128;
#pragma unroll
            for (int g = 0; g < 8; g++)
                cp_async16(drow + (((g ^ (r & 7)) << 4)), src + g * 8);
        }
    };

    const int wm = wid & 3;
    const int wn = wid >> 2;

    float acc[2][8][4];
#pragma unroll
    for (int a = 0; a < 2; a++)
#pragma unroll
        for (int b = 0; b < 8; b++)
#pragma unroll
            for (int cx = 0; cx < 4; cx++) acc[a][b][cx] = 0.f;

    load_stage(0, 0); CP_COMMIT();
    load_stage(1, 1); CP_COMMIT();

    for (int c = 0; c < 32; ++c) {
        if (c < 31) { CP_WAIT(1); } else { CP_WAIT(0); }
        __syncthreads();
        if (c + 2 < 32) { load_stage(c + 2, (c + 2) % 3); CP_COMMIT(); }

        const uint32_t st = sbase + (c % 3) * GT_STAGE;
#pragma unroll
        for (int ks = 0; ks < 4; ks++) {
            const int lr = lane & 15;
            const int g = ks * 2 + (lane >> 4);

            uint32_t ah[2][4], al[2][4];
#pragma unroll
            for (int mb = 0; mb < 2; mb++) {
                const int r = wm * 32 + mb * 16 + lr;
                const uint32_t off = r * 128 + (((g ^ (r & 7)) << 4));
                LDSM_X4(ah[mb], st + off);
                LDSM_X4(al[mb], st + GT_TILE + off);
            }
            uint32_t bhf[8][2], blf[8][2];
#pragma unroll
            for (int np = 0; np < 4; np++) {
                const int r = wn * 64 + np * 16 + lr;
                const uint32_t off = r * 128 + (((g ^ (r & 7)) << 4));
                uint32_t t4[4];
                LDSM_X4(t4, st + 2 * GT_TILE + off);
                bhf[2*np][0] = t4[0]; bhf[2*np][1] = t4[2];
                bhf[2*np+1][0] = t4[1]; bhf[2*np+1][1] = t4[3];
                LDSM_X4(t4, st + 3 * GT_TILE + off);
                blf[2*np][0] = t4[0]; blf[2*np][1] = t4[2];
                blf[2*np+1][0] = t4[1]; blf[2*np+1][1] = t4[3];
            }
#pragma unroll
            for (int mb = 0; mb < 2; mb++)
#pragma unroll
                for (int nb = 0; nb < 8; nb++) {
                    mma16816_bf(acc[mb][nb], ah[mb], bhf[nb]);
                    mma16816_bf(acc[mb][nb], ah[mb], blf[nb]);
                    mma16816_bf(acc[mb][nb], al[mb], bhf[nb]);
                }
        }
    }

    // ---------------- epilogue ----------------
    if (MODE == 0) {
#pragma unroll
        for (int mb = 0; mb < 2; mb++)
#pragma unroll
            for (int rh = 0; rh < 2; rh++) {
                const int row = wm * 32 + mb * 16 + rh * 8 + (lane >> 2);
                float* dst = C + (size_t)(mloc + row) * 2048 + nloc;
                const int cbase = wn * 64 + (lane & 3) * 2;
#pragma unroll
                for (int nb = 0; nb < 8; nb++)
                    *(float2*)(dst + cbase + nb * 8) =
                        make_float2(acc[mb][nb][rh * 2], acc[mb][nb][rh * 2 + 1]);
            }
    } else {
        // stage the 128x128 fp32 tile in smem
        __syncthreads();
        float* stg = (float*)smem;     // [128][132]
#pragma unroll
        for (int mb = 0; mb < 2; mb++)
#pragma unroll
            for (int rh = 0; rh < 2; rh++) {
                const int row = wm * 32 + mb * 16 + rh * 8 + (lane >> 2);
                const int cbase = wn * 64 + (lane & 3) * 2;
#pragma unroll
                for (int nb = 0; nb < 8; nb++) {
                    stg[row * 132 + cbase + nb * 8]     = acc[mb][nb][rh * 2];
                    stg[row * 132 + cbase + nb * 8 + 1] = acc[mb][nb][rh * 2 + 1];
                }
            }
        __syncthreads();

        if (wsel == 2) {
            // V: transposed fp16 -> g_Vth[bh][d][t], plus row-1535 fp32 save
            for (int idx = tid; idx < 128 * 128; idx += 256) {
                const int d = idx >> 7, r = idx & 127;   // consecutive tid -> consecutive t
                const int gr = mloc + r;
                const int bb = gr >> 11, t = gr & 2047;
                const float x = stg[r * 132 + d];
                g_Vth[((size_t)((bb * H_ + hsel) * D_ + d)) * T_ + t] = __float2half_rn(x);
                if (t == 1535) g_v1535[(bb * H_ + hsel) * 128 + d] = x;
            }
        } else {
            // Q/K: apply RoPE, emit bf16 hi/lo splits
            __nv_bfloat16* Oh = (wsel == 0) ? g_Qh : g_Kh;
            __nv_bfloat16* Ol = (wsel == 0) ? g_Ql : g_Kl;
            for (int idx = tid; idx < 128 * 64; idx += 256) {
                const int r = idx >> 6, j = idx & 63;
                const int gr = mloc + r;
                const int bb = gr >> 11, t = gr & 2047;
                const float inv = powf(10000.f, -(float)j * (1.f / 64.f));
                float s, cc;
                sincosf((float)t * inv, &s, &cc);
                const float x1 = stg[r * 132 + j];
                const float x2 = stg[r * 132 + j + 64];
                const float y1 = x1 * cc - x2 * s;
                const float y2 = x2 * cc + x1 * s;
                const size_t base = (((size_t)(bb * H_ + hsel) * T_ + t) << 7);
                __nv_bfloat16 h, l;
                split2(y1, h, l); Oh[base + j] = h;      Ol[base + j] = l;
                split2(y2, h, l); Oh[base + j + 64] = h; Ol[base + j + 64] = l;
            }
        }
    }
}

// ---------------- A_bar softmax + CAM bernoulli -> g_ve ----------------
__device__ __forceinline__ uint32_t rotl32(uint32_t x, int r) { return (x << r) | (x >> (32 - r)); }

__global__ void __launch_bounds__(256) abar_cam()
{
    const int bh = blockIdx.x;
    __shared__ float qrow[128];
    __shared__ float sc[2048];
    __shared__ float red[256];
    __shared__ float maskf;
    const int tid = threadIdx.x;

    const size_t qoff = ((size_t)bh * T_ + (T_ - 1)) * 128;
    if (tid < 128)
        qrow[tid] = __bfloat162float(g_Qh[qoff + tid]) + __bfloat162float(g_Ql[qoff + tid]);
    __syncthreads();

    for (int k = tid; k < 2048; k += 256) {
        const size_t koff = ((size_t)bh * T_ + k) * 128;
        const __nv_bfloat162* kh = (const __nv_bfloat162*)(g_Kh + koff);
        const __nv_bfloat162* kl = (const __nv_bfloat162*)(g_Kl + koff);
        float s = 0.f;
#pragma unroll
        for (int i = 0; i < 64; i++) {
            const __nv_bfloat162 a = kh[i], b = kl[i];
            const float kx = __bfloat162float(a.x) + __bfloat162float(b.x);
            const float ky = __bfloat162float(a.y) + __bfloat162float(b.y);
            s = fmaf(kx, qrow[2 * i], s);
            s = fmaf(ky, qrow[2 * i + 1], s);
        }
        sc[k] = s * 0.08838834764831845f;
    }
    __syncthreads();

    float m = -FLT_MAX;
    for (int k = tid; k < 2048; k += 256) m = fmaxf(m, sc[k]);
    red[tid] = m; __syncthreads();
    for (int o = 128; o > 0; o >>= 1) { if (tid < o) red[tid] = fmaxf(red[tid], red[tid + o]); __syncthreads(); }
    const float gm = red[0];
    __syncthreads();

    float sum = 0.f;
    for (int k = tid; k < 2048; k += 256) { const float p = expf(sc[k] - gm); sc[k] = p; sum += p; }
    red[tid] = sum; __syncthreads();
    for (int o = 128; o > 0; o >>= 1) { if (tid < o) red[tid] += red[tid + o]; __syncthreads(); }
    const float invs = 1.f / red[0];
    __syncthreads();

    for (int k = tid; k < 2048; k += 256) sc[k] *= invs;
    __syncthreads();

    float ws = 0.f;
    for (int k = 1536 + tid; k < 2048; k += 256) ws += sc[k];
    red[tid] = ws; __syncthreads();
    for (int o = 128; o > 0; o >>= 1) { if (tid < o) red[tid] += red[tid + o]; __syncthreads(); }

    if (tid == 0) {
        const float avg = fmaxf(red[0] * (1.f / 512.f), 1e-6f);
        float p = fminf(fmaxf(sc[1535] / avg, 0.f), 1.f);
        uint32_t x0 = 0u, x1 = (uint32_t)bh;
        const uint32_t k0 = 0u, k1 = 42u, k2 = 0x1BD11BDAu ^ k0 ^ k1;
        x0 += k0; x1 += k1;
#define TF4(a,b,c,d)  x0+=x1; x1=rotl32(x1,a); x1^=x0; \
                      x0+=x1; x1=rotl32(x1,b); x1^=x0; \
                      x0+=x1; x1=rotl32(x1,c); x1^=x0; \
                      x0+=x1; x1=rotl32(x1,d); x1^=x0;
        TF4(13,15,26,6)   x0 += k1; x1 += k2 + 1u;
        TF4(17,29,16,24)  x0 += k2; x1 += k0 + 2u;
        TF4(13,15,26,6)   x0 += k0; x1 += k1 + 3u;
        TF4(17,29,16,24)  x0 += k1; x1 += k2 + 4u;
        TF4(13,15,26,6)   x0 += k2; x1 += k0 + 5u;
#undef TF4
        const uint32_t bits = x0 ^ x1;
        float uu = __uint_as_float((bits >> 9) | 0x3f800000u) - 1.0f;
        uu = fmaxf(uu, 0.f);
        maskf = (uu < p) ? 1.f : 0.f;
    }
    __syncthreads();

    if (tid < 128)
        g_ve[bh * 128 + tid] = g_v1535[bh * 128 + tid] * maskf * (1.f / 512.f);
}

// CAM window update in-place on fp16 Vt: Vt[bh][d][k] += ve[bh][d], k in [1536,2048)
__global__ void vt_update()
{
    const int idx = blockIdx.x * blockDim.x + threadIdx.x;   // 1M half2
    const int bh = idx >> 15;              // /(128*256)
    const int rem = idx & 32767;
    const int d = rem >> 8;
    const int kk = rem & 255;
    const float ve = g_ve[bh * 128 + d];
    __half2* p = (__half2*)(g_Vth + ((size_t)(bh * 128 + d)) * 2048 + 1536) + kk;
    float2 x = __half22float2(*p);
    *p = __floats2half2_rn(x.x + ve, x.y + ve);
}

// ---------------- fused flash attention (mma) ----------------
#define FL_SMEM 229376

__global__ void __launch_bounds__(256) flash_mma()
{
    extern __shared__ char smem[];
    const uint32_t sb = smem_u32(smem);
    const uint32_t QS = sb, KS = sb + 65536, VS = sb + 196608;
    const int tid = threadIdx.x, wid = tid >> 5, lane = tid & 31;
    const int bh = blockIdx.y;
    const int qb = 15 - blockIdx.x;
    const int nkt = qb + 1;

    {
        const int part = tid >> 6, u = tid & 63;
        const int plane = part >> 1, c = part & 1;
        const __nv_bfloat16* base = (plane ? g_Ql : g_Qh) + ((size_t)(bh * 2048 + qb * 128)) * 128 + c * 64;
        const uint32_t dstt = QS + part * 16384;
#pragma unroll
        for (int rr = 0; rr < 2; rr++) {
            const int r = u * 2 + rr;
            const char* sp = (const char*)(base + (size_t)r * 128);
            const uint32_t drow = dstt + r * 128;
#pragma unroll
            for (int g = 0; g < 8; g++) cp_async16(drow + ((g ^ (r & 7)) << 4), sp + g * 16);
        }
    }
    CP_COMMIT();

    auto loadK = [&](int j, int s) {
        const int part = tid >> 6, u = tid & 63;
        const int plane = part >> 1, c = part & 1;
        const __nv_bfloat16* base = (plane ? g_Kl : g_Kh) + ((size_t)(bh * 2048 + j * 128)) * 128 + c * 64;
        const uint32_t dstt = KS + s * 65536 + part * 16384;
#pragma unroll
        for (int rr = 0; rr < 2; rr++) {
            const int r = u * 2 + rr;
            const char* sp = (const char*)(base + (size_t)r * 128);
            const uint32_t drow = dstt + r * 128;
#pragma unroll
            for (int g = 0; g < 8; g++) cp_async16(drow + ((g ^ (r & 7)) << 4), sp + g * 16);
        }
    };
    auto loadV = [&](int j) {
        const int c = tid >> 7, r = tid & 127;
        const char* sp = (const char*)(g_Vth + ((size_t)(bh * 128 + r)) * 2048 + j * 128 + c * 64);
        const uint32_t drow = VS + c * 16384 + r * 128;
#pragma unroll
        for (int g = 0; g < 8; g++) cp_async16(drow + ((g ^ (r & 7)) << 4), sp + g * 16);
    };

    loadK(0, 0); CP_COMMIT();
    loadV(0);    CP_COMMIT();

    float oacc[16][4];
#pragma unroll
    for (int nt = 0; nt < 16; nt++)
#pragma unroll
        for (int e = 0; e < 4; e++) oacc[nt][e] = 0.f;
    float m0 = -1e30f, m1 = -1e30f, l0 = 0.f, l1 = 0.f;
    uint32_t pfrag[8][4];

    const float scale = 0.08838834764831845f;
    const int lr = lane & 15;
    const int rloc = (lane >> 2);
    const int colloc = (lane & 3) * 2;

    for (int j = 0; j < nkt; j++) {
        const int sK = j & 1;
        CP_WAIT(1);            // K(j) done; V(j) may still be in flight
        __syncthreads();
        if (j + 1 < nkt) { loadK(j + 1, sK ^ 1); CP_COMMIT(); }   // overlaps S-mma

        float sacc[16][4];
#pragma unroll
        for (int nt = 0; nt < 16; nt++)
#pragma unroll
            for (int e = 0; e < 4; e++) sacc[nt][e] = 0.f;

        const uint32_t kst = KS + sK * 65536;
#pragma unroll
        for (int ks = 0; ks < 8; ks++) {
            const int chunk = ks >> 2;
            const int g = (ks & 3) * 2 + (lane >> 4);
            const int ar = wid * 16 + lr;
            const uint32_t aoff = ar * 128 + ((g ^ (ar & 7)) << 4);
            uint32_t ahi[4], alo[4];
            LDSM_X4(ahi, QS + chunk * 16384 + aoff);
            LDSM_X4(alo, QS + (2 + chunk) * 16384 + aoff);
#pragma unroll
            for (int np = 0; np < 8; np++) {
                const int br = np * 16 + lr;
                const uint32_t boff = br * 128 + ((g ^ (br & 7)) << 4);
                uint32_t t4[4], u4[4];
                LDSM_X4(t4, kst + chunk * 16384 + boff);
                LDSM_X4(u4, kst + (2 + chunk) * 16384 + boff);
                {
                    uint32_t b0[2] = { t4[0], t4[2] };
                    uint32_t c0_[2] = { u4[0], u4[2] };
                    mma16816_bf(sacc[2*np], ahi, b0);
                    mma16816_bf(sacc[2*np], ahi, c0_);
                    mma16816_bf(sacc[2*np], alo, b0);
                }
                {
                    uint32_t b1[2] = { t4[1], t4[3] };
                    uint32_t c1_[2] = { u4[1], u4[3] };
                    mma16816_bf(sacc[2*np+1], ahi, b1);
                    mma16816_bf(sacc[2*np+1], ahi, c1_);
                    mma16816_bf(sacc[2*np+1], alo, b1);
                }
            }
        }

        const bool diag = (j == qb);
        const int rg0 = wid * 16 + rloc;
#pragma unroll
        for (int nt = 0; nt < 16; nt++) {
            float* s = sacc[nt];
            s[0] *= scale; s[1] *= scale; s[2] *= scale; s[3] *= scale;
            if (diag) {
                const int cl = nt * 8 + colloc;
                if (cl     > rg0)     s[0] = -1e30f;
                if (cl + 1 > rg0)     s[1] = -1e30f;
                if (cl     > rg0 + 8) s[2] = -1e30f;
                if (cl + 1 > rg0 + 8) s[3] = -1e30f;
            }
        }

        float mx0 = -1e30f, mx1 = -1e30f;
#pragma unroll
        for (int nt = 0; nt < 16; nt++) {
            mx0 = fmaxf(mx0, fmaxf(sacc[nt][0], sacc[nt][1]));
            mx1 = fmaxf(mx1, fmaxf(sacc[nt][2], sacc[nt][3]));
        }
        mx0 = fmaxf(mx0, __shfl_xor_sync(0xffffffffu, mx0, 1));
        mx0 = fmaxf(mx0, __shfl_xor_sync(0xffffffffu, mx0, 2));
        mx1 = fmaxf(mx1, __shfl_xor_sync(0xffffffffu, mx1, 1));
        mx1 = fmaxf(mx1, __shfl_xor_sync(0xffffffffu, mx1, 2));
        const float mn0 = fmaxf(m0, mx0), mn1 = fmaxf(m1, mx1);
        const float cr0 = __expf(m0 - mn0), cr1 = __expf(m1 - mn1);
        l0 *= cr0; l1 *= cr1; m0 = mn0; m1 = mn1;
#pragma unroll
        for (int nt = 0; nt < 16; nt++) {
            oacc[nt][0] *= cr0; oacc[nt][1] *= cr0;
            oacc[nt][2] *= cr1; oacc[nt][3] *= cr1;
        }
        float ps0 = 0.f, ps1 = 0.f;
#pragma unroll
        for (int kb = 0; kb < 8; kb++) {
            const float p00 = __expf(sacc[2*kb][0]   - mn0), p01 = __expf(sacc[2*kb][1]   - mn0);
            const float p02 = __expf(sacc[2*kb][2]   - mn1), p03 = __expf(sacc[2*kb][3]   - mn1);
            const float p10 = __expf(sacc[2*kb+1][0] - mn0), p11 = __expf(sacc[2*kb+1][1] - mn0);
            const float p12 = __expf(sacc[2*kb+1][2] - mn1), p13 = __expf(sacc[2*kb+1][3] - mn1);
            pfrag[kb][0] = packh2(p00, p01);
            pfrag[kb][1] = packh2(p02, p03);
            pfrag[kb][2] = packh2(p10, p11);
            pfrag[kb][3] = packh2(p12, p13);
            ps0 += p00 + p01 + p10 + p11;
            ps1 += p02 + p03 + p12 + p13;
        }
        ps0 += __shfl_xor_sync(0xffffffffu, ps0, 1);
        ps0 += __shfl_xor_sync(0xffffffffu, ps0, 2);
        ps1 += __shfl_xor_sync(0xffffffffu, ps1, 1);
        ps1 += __shfl_xor_sync(0xffffffffu, ps1, 2);
        l0 += ps0; l1 += ps1;

        // wait for V(j): one group (K(j+1)) may remain in flight
        if (j + 1 < nkt) { CP_WAIT(1); } else { CP_WAIT(0); }
        __syncthreads();

#pragma unroll
        for (int kb = 0; kb < 8; kb++) {
            const int chunk = kb >> 2;
            const int g = (kb & 3) * 2 + (lane >> 4);
#pragma unroll
            for (int np = 0; np < 8; np++) {
                const int br = np * 16 + lr;
                const uint32_t boff = br * 128 + ((g ^ (br & 7)) << 4);
                uint32_t t4[4];
                LDSM_X4(t4, VS + chunk * 16384 + boff);
                uint32_t b0[2] = { t4[0], t4[2] };
                uint32_t b1[2] = { t4[1], t4[3] };
                mma16816_fp(oacc[2*np],   pfrag[kb], b0);
                mma16816_fp(oacc[2*np+1], pfrag[kb], b1);
            }
        }
        __syncthreads();
        if (j + 1 < nkt) { loadV(j + 1); CP_COMMIT(); }
    }

    // ---- writeout: bf16 hi/lo splits of AO ----
    const float inv0 = 1.f / l0, inv1 = 1.f / l1;
    const int bb = bh >> 4, hh = bh & 15;
    const int rgg0 = qb * 128 + wid * 16 + rloc;
    const size_t base0 = ((size_t)(bb * 2048 + rgg0)) * 2048 + hh * 128;
    const size_t base1 = base0 + (size_t)8 * 2048;
#pragma unroll
    for (int nt = 0; nt < 16; nt++) {
        const int d = nt * 8 + colloc;
        __nv_bfloat16 h0, l0_, h1, l1_;
        split2(oacc[nt][0] * inv0, h0, l0_);
        split2(oacc[nt][1] * inv0, h1, l1_);
        *(__nv_bfloat162*)(g_AOh + base0 + d) = __nv_bfloat162(h0, h1);
        *(__nv_bfloat162*)(g_AOl + base0 + d) = __nv_bfloat162(l0_, l1_);
        split2(oacc[nt][2] * inv1, h0, l0_);
        split2(oacc[nt][3] * inv1, h1, l1_);
        *(__nv_bfloat162*)(g_AOh + base1 + d) = __nv_bfloat162(h0, h1);
        *(__nv_bfloat162*)(g_AOl + base1 + d) = __nv_bfloat162(l0_, l1_);
    }
}

// ---------------- launch ----------------
extern "C" void kernel_launch(void* const* d_in, const int* in_sizes, int n_in,
                              void* d_out, int out_size)
{
    (void)in_sizes; (void)n_in; (void)out_size;
    const float* hidden = (const float*)d_in[0];
    const float* q_w = (const float*)d_in[2];
    const float* k_w = (const float*)d_in[3];
    const float* v_w = (const float*)d_in[4];
    const float* o_w = (const float*)d_in[5];
    float* out = (float*)d_out;

    cudaFuncSetAttribute(gemm_mma<0>, cudaFuncAttributeMaxDynamicSharedMemorySize, GT_SMEM);
    cudaFuncSetAttribute(gemm_mma<1>, cudaFuncAttributeMaxDynamicSharedMemorySize, GT_SMEM);
    cudaFuncSetAttribute(flash_mma, cudaFuncAttributeMaxDynamicSharedMemorySize, FL_SMEM);

    convert_all<<<dim3(8192, 5), 256>>>(hidden, q_w, k_w, v_w, o_w);
    gemm_mma<1><<<dim3(48, 32), 256, GT_SMEM>>>(nullptr);
    abar_cam<<<32, 256>>>();
    vt_update<<<4096, 256>>>();
    flash_mma<<<dim3(16, 32), 256, FL_SMEM>>>();
    gemm_mma<0><<<dim3(16, 32), 256, GT_SMEM>>>(out);
}

// round 12
// speedup vs baseline: 1.2302x; 1.2302x over previous
#include <cuda_runtime.h>
#include <cuda_bf16.h>
#include <cuda_fp16.h>
#include <math.h>
#include <stdint.h>
#include <float.h>

#define B_  2
#define T_  2048
#define HID_ 2048
#define H_  16
#define D_  128
#define BH_ (B_*H_)
#define BT_ (B_*T_)

// ---------------- device scratch ----------------
__device__ float g_ve[BH_ * D_];
__device__ float g_v1535[BH_ * D_];

// bf16 split operands (QKV projection only)
__device__ __align__(16) __nv_bfloat16 g_Hh[(size_t)BT_ * HID_];
__device__ __align__(16) __nv_bfloat16 g_Hl[(size_t)BT_ * HID_];
__device__ __align__(16) __nv_bfloat16 g_Wh[3][(size_t)HID_ * HID_];
__device__ __align__(16) __nv_bfloat16 g_Wl[3][(size_t)HID_ * HID_];
// fp16 operands
__device__ __align__(16) __half g_OWfh[(size_t)HID_ * HID_];   // o_w fp16
__device__ __align__(16) __half g_AOfh[(size_t)BT_ * HID_];    // attn out fp16
__device__ __align__(16) __half g_Qh[(size_t)BH_ * T_ * D_];   // fp16 hi
__device__ __align__(16) __half g_Ql[(size_t)BH_ * T_ * D_];   // fp16 lo (abar only)
__device__ __align__(16) __half g_Kh[(size_t)BH_ * T_ * D_];
__device__ __align__(16) __half g_Kl[(size_t)BH_ * T_ * D_];
__device__ __align__(16) __half g_Vth[(size_t)BH_ * D_ * T_];  // Vt[bh][d][k]

// ---------------- PTX helpers (compute_103-safe) ----------------
__device__ __forceinline__ uint32_t smem_u32(const void* p) {
    uint32_t a;
    asm("{ .reg .u64 t; cvta.to.shared.u64 t, %1; cvt.u32.u64 %0, t; }" : "=r"(a) : "l"(p));
    return a;
}
__device__ __forceinline__ void cp_async16(uint32_t dst, const void* src) {
    asm volatile("cp.async.cg.shared.global [%0], [%1], 16;" :: "r"(dst), "l"(src));
}
#define CP_COMMIT() asm volatile("cp.async.commit_group;" ::: "memory")
#define CP_WAIT(N)  asm volatile("cp.async.wait_group %0;" :: "n"(N) : "memory")

#define LDSM_X4(r, addr) \
    asm volatile("ldmatrix.sync.aligned.m8n8.x4.shared.b16 {%0,%1,%2,%3}, [%4];" \
        : "=r"((r)[0]), "=r"((r)[1]), "=r"((r)[2]), "=r"((r)[3]) : "r"(addr))

__device__ __forceinline__ void mma16816_bf(float* c, const uint32_t* a, const uint32_t* b) {
    asm volatile("mma.sync.aligned.m16n8k16.row.col.f32.bf16.bf16.f32 "
        "{%0,%1,%2,%3}, {%4,%5,%6,%7}, {%8,%9}, {%0,%1,%2,%3};"
        : "+f"(c[0]), "+f"(c[1]), "+f"(c[2]), "+f"(c[3])
        : "r"(a[0]), "r"(a[1]), "r"(a[2]), "r"(a[3]), "r"(b[0]), "r"(b[1]));
}
__device__ __forceinline__ void mma16816_fp(float* c, const uint32_t* a, const uint32_t* b) {
    asm volatile("mma.sync.aligned.m16n8k16.row.col.f32.f16.f16.f32 "
        "{%0,%1,%2,%3}, {%4,%5,%6,%7}, {%8,%9}, {%0,%1,%2,%3};"
        : "+f"(c[0]), "+f"(c[1]), "+f"(c[2]), "+f"(c[3])
        : "r"(a[0]), "r"(a[1]), "r"(a[2]), "r"(a[3]), "r"(b[0]), "r"(b[1]));
}

__device__ __forceinline__ void split2(float x, __nv_bfloat16& h, __nv_bfloat16& l) {
    h = __float2bfloat16(x);
    l = __float2bfloat16(x - __bfloat162float(h));
}
__device__ __forceinline__ void split2h(float x, __half& h, __half& l) {
    h = __float2half_rn(x);
    l = __float2half_rn(x - __half2float(h));
}
__device__ __forceinline__ uint32_t packh2(float a, float b) {
    __half2 h = __floats2half2_rn(a, b);
    return *reinterpret_cast<uint32_t*>(&h);
}

// ---------------- input conversions ----------------
// sel 0..3: bf16 hi/lo splits (hidden, q_w, k_w, v_w). sel 4: o_w -> fp16 single.
__global__ void convert_all(const float* __restrict__ hs,
                            const float* __restrict__ qw, const float* __restrict__ kw,
                            const float* __restrict__ vw, const float* __restrict__ ow)
{
    const int sel = blockIdx.y;
    if (sel > 0 && blockIdx.x >= 4096) return;
    const size_t i = ((size_t)blockIdx.x * blockDim.x + threadIdx.x) * 4;
    if (sel == 4) {
        const float4 v = *(const float4*)(ow + i);
        *(__half2*)(g_OWfh + i)     = __floats2half2_rn(v.x, v.y);
        *(__half2*)(g_OWfh + i + 2) = __floats2half2_rn(v.z, v.w);
        return;
    }
    const float* s;
    __nv_bfloat16 *hi, *lo;
    switch (sel) {
        case 0: s = hs; hi = g_Hh;    lo = g_Hl;    break;
        case 1: s = qw; hi = g_Wh[0]; lo = g_Wl[0]; break;
        case 2: s = kw; hi = g_Wh[1]; lo = g_Wl[1]; break;
        default: s = vw; hi = g_Wh[2]; lo = g_Wl[2]; break;
    }
    const float4 v = *(const float4*)(s + i);
    __nv_bfloat16 h0,h1,h2,h3,l0,l1,l2,l3;
    split2(v.x,h0,l0); split2(v.y,h1,l1); split2(v.z,h2,l2); split2(v.w,h3,l3);
    *(__nv_bfloat162*)(hi + i)     = __nv_bfloat162(h0, h1);
    *(__nv_bfloat162*)(hi + i + 2) = __nv_bfloat162(h2, h3);
    *(__nv_bfloat162*)(lo + i)     = __nv_bfloat162(l0, l1);
    *(__nv_bfloat162*)(lo + i + 2) = __nv_bfloat162(l2, l3);
}

// ---------------- mma.sync GEMM, 3-stage pipeline ----------------
// MODE 1: QKV proj, bf16 3-term, grid(48,32): x=(w*16+n).
//         Q/K: rope fused -> fp16 hi/lo. V: fp16 transposed + row-1535 save.
// MODE 0: O proj, fp16 1-term, grid(16,32) -> C (d_out)
#define GT_TILE  16384

template<int MODE>
__global__ void __launch_bounds__(256) gemm_mma(float* __restrict__ C)
{
    constexpr int NT = (MODE == 1) ? 4 : 2;
    constexpr uint32_t STAGE = NT * GT_TILE;
    constexpr int TPP = 256 / NT;
    constexpr int RPT = 128 / TPP;

    extern __shared__ char smem[];
    const uint32_t sbase = smem_u32(smem);
    const int tid = threadIdx.x;
    const int wid = tid >> 5;
    const int lane = tid & 31;

    int wsel = 0, hsel = 0, mloc, nloc;
    if (MODE == 1) {
        wsel = blockIdx.x >> 4;
        hsel = blockIdx.x & 15;
        mloc = blockIdx.y * 128; nloc = hsel * 128;
    } else {
        mloc = blockIdx.y * 128; nloc = blockIdx.x * 128;
    }

    const int part = tid / TPP;
    const int u = tid % TPP;
    const char* gsrc;
    if (MODE == 1) {
        gsrc = (part == 0) ? (const char*)g_Hh : (part == 1) ? (const char*)g_Hl
             : (part == 2) ? (const char*)g_Wh[wsel] : (const char*)g_Wl[wsel];
    } else {
        gsrc = (part == 0) ? (const char*)g_AOfh : (const char*)g_OWfh;
    }
    const int growbase = (part < NT / 2) ? mloc : nloc;
    const uint32_t tpart = sbase + part * GT_TILE;

    auto load_stage = [&](int c, int s) {
#pragma unroll
        for (int rr = 0; rr < RPT; rr++) {
            const int r = u * RPT + rr;
            const char* src = gsrc + ((size_t)(growbase + r) * 2048 + c * 64) * 2;
            const uint32_t drow = tpart + s * STAGE + r * 128;
#pragma unroll
            for (int g = 0; g < 8; g++)
                cp_async16(drow + (((g ^ (r & 7)) << 4)), src + g * 16);
        }
    };

    const int wm = wid & 3;
    const int wn = wid >> 2;

    float acc[2][8][4];
#pragma unroll
    for (int a = 0; a < 2; a++)
#pragma unroll
        for (int b = 0; b < 8; b++)
#pragma unroll
            for (int cx = 0; cx < 4; cx++) acc[a][b][cx] = 0.f;

    load_stage(0, 0); CP_COMMIT();
    load_stage(1, 1); CP_COMMIT();

    for (int c = 0; c < 32; ++c) {
        if (c < 31) { CP_WAIT(1); } else { CP_WAIT(0); }
        __syncthreads();
        if (c + 2 < 32) { load_stage(c + 2, (c + 2) % 3); CP_COMMIT(); }

        const uint32_t st = sbase + (c % 3) * STAGE;
#pragma unroll
        for (int ks = 0; ks < 4; ks++) {
            const int lr = lane & 15;
            const int g = ks * 2 + (lane >> 4);

            uint32_t ah[2][4], al[2][4];
#pragma unroll
            for (int mb = 0; mb < 2; mb++) {
                const int r = wm * 32 + mb * 16 + lr;
                const uint32_t off = r * 128 + (((g ^ (r & 7)) << 4));
                LDSM_X4(ah[mb], st + off);
                if (MODE == 1) LDSM_X4(al[mb], st + GT_TILE + off);
            }
            uint32_t bhf[8][2], blf[8][2];
#pragma unroll
            for (int np = 0; np < 4; np++) {
                const int r = wn * 64 + np * 16 + lr;
                const uint32_t off = r * 128 + (((g ^ (r & 7)) << 4));
                uint32_t t4[4];
                LDSM_X4(t4, st + (NT / 2) * GT_TILE + off);
                bhf[2*np][0] = t4[0]; bhf[2*np][1] = t4[2];
                bhf[2*np+1][0] = t4[1]; bhf[2*np+1][1] = t4[3];
                if (MODE == 1) {
                    LDSM_X4(t4, st + 3 * GT_TILE + off);
                    blf[2*np][0] = t4[0]; blf[2*np][1] = t4[2];
                    blf[2*np+1][0] = t4[1]; blf[2*np+1][1] = t4[3];
                }
            }
#pragma unroll
            for (int mb = 0; mb < 2; mb++)
#pragma unroll
                for (int nb = 0; nb < 8; nb++) {
                    if (MODE == 1) {
                        mma16816_bf(acc[mb][nb], ah[mb], bhf[nb]);
                        mma16816_bf(acc[mb][nb], ah[mb], blf[nb]);
                        mma16816_bf(acc[mb][nb], al[mb], bhf[nb]);
                    } else {
                        mma16816_fp(acc[mb][nb], ah[mb], bhf[nb]);
                    }
                }
        }
    }

    // ---------------- epilogue ----------------
    if (MODE == 0) {
#pragma unroll
        for (int mb = 0; mb < 2; mb++)
#pragma unroll
            for (int rh = 0; rh < 2; rh++) {
                const int row = wm * 32 + mb * 16 + rh * 8 + (lane >> 2);
                float* dst = C + (size_t)(mloc + row) * 2048 + nloc;
                const int cbase = wn * 64 + (lane & 3) * 2;
#pragma unroll
                for (int nb = 0; nb < 8; nb++)
                    *(float2*)(dst + cbase + nb * 8) =
                        make_float2(acc[mb][nb][rh * 2], acc[mb][nb][rh * 2 + 1]);
            }
    } else {
        __syncthreads();
        float* stg = (float*)smem;     // [128][132]
#pragma unroll
        for (int mb = 0; mb < 2; mb++)
#pragma unroll
            for (int rh = 0; rh < 2; rh++) {
                const int row = wm * 32 + mb * 16 + rh * 8 + (lane >> 2);
                const int cbase = wn * 64 + (lane & 3) * 2;
#pragma unroll
                for (int nb = 0; nb < 8; nb++) {
                    stg[row * 132 + cbase + nb * 8]     = acc[mb][nb][rh * 2];
                    stg[row * 132 + cbase + nb * 8 + 1] = acc[mb][nb][rh * 2 + 1];
                }
            }
        __syncthreads();

        if (wsel == 2) {
            for (int idx = tid; idx < 128 * 128; idx += 256) {
                const int d = idx >> 7, r = idx & 127;
                const int gr = mloc + r;
                const int bb = gr >> 11, t = gr & 2047;
                const float x = stg[r * 132 + d];
                g_Vth[((size_t)((bb * H_ + hsel) * D_ + d)) * T_ + t] = __float2half_rn(x);
                if (t == 1535) g_v1535[(bb * H_ + hsel) * 128 + d] = x;
            }
        } else {
            __half* Oh = (wsel == 0) ? g_Qh : g_Kh;
            __half* Ol = (wsel == 0) ? g_Ql : g_Kl;
            for (int idx = tid; idx < 128 * 64; idx += 256) {
                const int r = idx >> 6, j = idx & 63;
                const int gr = mloc + r;
                const int bb = gr >> 11, t = gr & 2047;
                const float inv = powf(10000.f, -(float)j * (1.f / 64.f));
                float s, cc;
                sincosf((float)t * inv, &s, &cc);
                const float x1 = stg[r * 132 + j];
                const float x2 = stg[r * 132 + j + 64];
                const float y1 = x1 * cc - x2 * s;
                const float y2 = x2 * cc + x1 * s;
                const size_t base = (((size_t)(bb * H_ + hsel) * T_ + t) << 7);
                __half h, l;
                split2h(y1, h, l); Oh[base + j] = h;      Ol[base + j] = l;
                split2h(y2, h, l); Oh[base + j + 64] = h; Ol[base + j + 64] = l;
            }
        }
    }
}

// ---------------- A_bar softmax + CAM bernoulli -> g_ve ----------------
__device__ __forceinline__ uint32_t rotl32(uint32_t x, int r) { return (x << r) | (x >> (32 - r)); }

__global__ void __launch_bounds__(256) abar_cam()
{
    const int bh = blockIdx.x;
    __shared__ float qrow[128];
    __shared__ float sc[2048];
    __shared__ float red[256];
    __shared__ float maskf;
    const int tid = threadIdx.x;

    const size_t qoff = ((size_t)bh * T_ + (T_ - 1)) * 128;
    if (tid < 128)
        qrow[tid] = __half2float(g_Qh[qoff + tid]) + __half2float(g_Ql[qoff + tid]);
    __syncthreads();

    for (int k = tid; k < 2048; k += 256) {
        const size_t koff = ((size_t)bh * T_ + k) * 128;
        const __half2* kh = (const __half2*)(g_Kh + koff);
        const __half2* kl = (const __half2*)(g_Kl + koff);
        float s = 0.f;
#pragma unroll
        for (int i = 0; i < 64; i++) {
            const float2 a = __half22float2(kh[i]);
            const float2 b = __half22float2(kl[i]);
            s = fmaf(a.x + b.x, qrow[2 * i], s);
            s = fmaf(a.y + b.y, qrow[2 * i + 1], s);
        }
        sc[k] = s * 0.08838834764831845f;
    }
    __syncthreads();

    float m = -FLT_MAX;
    for (int k = tid; k < 2048; k += 256) m = fmaxf(m, sc[k]);
    red[tid] = m; __syncthreads();
    for (int o = 128; o > 0; o >>= 1) { if (tid < o) red[tid] = fmaxf(red[tid], red[tid + o]); __syncthreads(); }
    const float gm = red[0];
    __syncthreads();

    float sum = 0.f;
    for (int k = tid; k < 2048; k += 256) { const float p = expf(sc[k] - gm); sc[k] = p; sum += p; }
    red[tid] = sum; __syncthreads();
    for (int o = 128; o > 0; o >>= 1) { if (tid < o) red[tid] += red[tid + o]; __syncthreads(); }
    const float invs = 1.f / red[0];
    __syncthreads();

    for (int k = tid; k < 2048; k += 256) sc[k] *= invs;
    __syncthreads();

    float ws = 0.f;
    for (int k = 1536 + tid; k < 2048; k += 256) ws += sc[k];
    red[tid] = ws; __syncthreads();
    for (int o = 128; o > 0; o >>= 1) { if (tid < o) red[tid] += red[tid + o]; __syncthreads(); }

    if (tid == 0) {
        const float avg = fmaxf(red[0] * (1.f / 512.f), 1e-6f);
        float p = fminf(fmaxf(sc[1535] / avg, 0.f), 1.f);
        uint32_t x0 = 0u, x1 = (uint32_t)bh;
        const uint32_t k0 = 0u, k1 = 42u, k2 = 0x1BD11BDAu ^ k0 ^ k1;
        x0 += k0; x1 += k1;
#define TF4(a,b,c,d)  x0+=x1; x1=rotl32(x1,a); x1^=x0; \
                      x0+=x1; x1=rotl32(x1,b); x1^=x0; \
                      x0+=x1; x1=rotl32(x1,c); x1^=x0; \
                      x0+=x1; x1=rotl32(x1,d); x1^=x0;
        TF4(13,15,26,6)   x0 += k1; x1 += k2 + 1u;
        TF4(17,29,16,24)  x0 += k2; x1 += k0 + 2u;
        TF4(13,15,26,6)   x0 += k0; x1 += k1 + 3u;
        TF4(17,29,16,24)  x0 += k1; x1 += k2 + 4u;
        TF4(13,15,26,6)   x0 += k2; x1 += k0 + 5u;
#undef TF4
        const uint32_t bits = x0 ^ x1;
        float uu = __uint_as_float((bits >> 9) | 0x3f800000u) - 1.0f;
        uu = fmaxf(uu, 0.f);
        maskf = (uu < p) ? 1.f : 0.f;
    }
    __syncthreads();

    if (tid < 128)
        g_ve[bh * 128 + tid] = g_v1535[bh * 128 + tid] * maskf * (1.f / 512.f);
}

// CAM window update in-place on fp16 Vt
__global__ void vt_update()
{
    const int idx = blockIdx.x * blockDim.x + threadIdx.x;
    const int bh = idx >> 15;
    const int rem = idx & 32767;
    const int d = rem >> 8;
    const int kk = rem & 255;
    const float ve = g_ve[bh * 128 + d];
    __half2* p = (__half2*)(g_Vth + ((size_t)(bh * 128 + d)) * 2048 + 1536) + kk;
    float2 x = __half22float2(*p);
    *p = __floats2half2_rn(x.x + ve, x.y + ve);
}

// ---------------- fused flash attention (fp16 S + fp16 PV) ----------------
// smem: Q 32KB + K 2x32KB + V 32KB = 128KB
#define FL_SMEM 131072

__global__ void __launch_bounds__(256) flash_mma()
{
    extern __shared__ char smem[];
    const uint32_t sb = smem_u32(smem);
    const uint32_t QS = sb, KS = sb + 32768, VS = sb + 98304;
    const int tid = threadIdx.x, wid = tid >> 5, lane = tid & 31;
    const int bh = blockIdx.y;
    const int qb = 15 - blockIdx.x;
    const int nkt = qb + 1;

    // Q preload (fp16 hi plane, 2 chunks of 64 cols)
    {
        const int c = tid >> 7, r = tid & 127;
        const char* sp = (const char*)(g_Qh + ((size_t)(bh * 2048 + qb * 128 + r)) * 128 + c * 64);
        const uint32_t drow = QS + c * 16384 + r * 128;
#pragma unroll
        for (int g = 0; g < 8; g++) cp_async16(drow + ((g ^ (r & 7)) << 4), sp + g * 16);
    }
    CP_COMMIT();

    auto loadK = [&](int j, int s) {
        const int c = tid >> 7, r = tid & 127;
        const char* sp = (const char*)(g_Kh + ((size_t)(bh * 2048 + j * 128 + r)) * 128 + c * 64);
        const uint32_t drow = KS + s * 32768 + c * 16384 + r * 128;
#pragma unroll
        for (int g = 0; g < 8; g++) cp_async16(drow + ((g ^ (r & 7)) << 4), sp + g * 16);
    };
    auto loadV = [&](int j) {
        const int c = tid >> 7, r = tid & 127;
        const char* sp = (const char*)(g_Vth + ((size_t)(bh * 128 + r)) * 2048 + j * 128 + c * 64);
        const uint32_t drow = VS + c * 16384 + r * 128;
#pragma unroll
        for (int g = 0; g < 8; g++) cp_async16(drow + ((g ^ (r & 7)) << 4), sp + g * 16);
    };

    loadK(0, 0); CP_COMMIT();
    loadV(0);    CP_COMMIT();

    float oacc[16][4];
#pragma unroll
    for (int nt = 0; nt < 16; nt++)
#pragma unroll
        for (int e = 0; e < 4; e++) oacc[nt][e] = 0.f;
    float m0 = -1e30f, m1 = -1e30f, l0 = 0.f, l1 = 0.f;
    uint32_t pfrag[8][4];

    const float scale = 0.08838834764831845f;
    const int lr = lane & 15;
    const int rloc = (lane >> 2);
    const int colloc = (lane & 3) * 2;

    for (int j = 0; j < nkt; j++) {
        const int sK = j & 1;
        CP_WAIT(1);
        __syncthreads();
        if (j + 1 < nkt) { loadK(j + 1, sK ^ 1); CP_COMMIT(); }

        float sacc[16][4];
#pragma unroll
        for (int nt = 0; nt < 16; nt++)
#pragma unroll
            for (int e = 0; e < 4; e++) sacc[nt][e] = 0.f;

        const uint32_t kst = KS + sK * 32768;
#pragma unroll
        for (int ks = 0; ks < 8; ks++) {
            const int chunk = ks >> 2;
            const int g = (ks & 3) * 2 + (lane >> 4);
            const int ar = wid * 16 + lr;
            const uint32_t aoff = ar * 128 + ((g ^ (ar & 7)) << 4);
            uint32_t ah[4];
            LDSM_X4(ah, QS + chunk * 16384 + aoff);
#pragma unroll
            for (int np = 0; np < 8; np++) {
                const int br = np * 16 + lr;
                const uint32_t boff = br * 128 + ((g ^ (br & 7)) << 4);
                uint32_t t4[4];
                LDSM_X4(t4, kst + chunk * 16384 + boff);
                uint32_t b0[2] = { t4[0], t4[2] };
                uint32_t b1[2] = { t4[1], t4[3] };
                mma16816_fp(sacc[2*np],   ah, b0);
                mma16816_fp(sacc[2*np+1], ah, b1);
            }
        }

        const bool diag = (j == qb);
        const int rg0 = wid * 16 + rloc;
#pragma unroll
        for (int nt = 0; nt < 16; nt++) {
            float* s = sacc[nt];
            s[0] *= scale; s[1] *= scale; s[2] *= scale; s[3] *= scale;
            if (diag) {
                const int cl = nt * 8 + colloc;
                if (cl     > rg0)     s[0] = -1e30f;
                if (cl + 1 > rg0)     s[1] = -1e30f;
                if (cl     > rg0 + 8) s[2] = -1e30f;
                if (cl + 1 > rg0 + 8) s[3] = -1e30f;
            }
        }

        float mx0 = -1e30f, mx1 = -1e30f;
#pragma unroll
        for (int nt = 0; nt < 16; nt++) {
            mx0 = fmaxf(mx0, fmaxf(sacc[nt][0], sacc[nt][1]));
            mx1 = fmaxf(mx1, fmaxf(sacc[nt][2], sacc[nt][3]));
        }
        mx0 = fmaxf(mx0, __shfl_xor_sync(0xffffffffu, mx0, 1));
        mx0 = fmaxf(mx0, __shfl_xor_sync(0xffffffffu, mx0, 2));
        mx1 = fmaxf(mx1, __shfl_xor_sync(0xffffffffu, mx1, 1));
        mx1 = fmaxf(mx1, __shfl_xor_sync(0xffffffffu, mx1, 2));
        const float mn0 = fmaxf(m0, mx0), mn1 = fmaxf(m1, mx1);
        const float cr0 = __expf(m0 - mn0), cr1 = __expf(m1 - mn1);
        l0 *= cr0; l1 *= cr1; m0 = mn0; m1 = mn1;
#pragma unroll
        for (int nt = 0; nt < 16; nt++) {
            oacc[nt][0] *= cr0; oacc[nt][1] *= cr0;
            oacc[nt][2] *= cr1; oacc[nt][3] *= cr1;
        }
        float ps0 = 0.f, ps1 = 0.f;
#pragma unroll
        for (int kb = 0; kb < 8; kb++) {
            const float p00 = __expf(sacc[2*kb][0]   - mn0), p01 = __expf(sacc[2*kb][1]   - mn0);
            const float p02 = __expf(sacc[2*kb][2]   - mn1), p03 = __expf(sacc[2*kb][3]   - mn1);
            const float p10 = __expf(sacc[2*kb+1][0] - mn0), p11 = __expf(sacc[2*kb+1][1] - mn0);
            const float p12 = __expf(sacc[2*kb+1][2] - mn1), p13 = __expf(sacc[2*kb+1][3] - mn1);
            pfrag[kb][0] = packh2(p00, p01);
            pfrag[kb][1] = packh2(p02, p03);
            pfrag[kb][2] = packh2(p10, p11);
            pfrag[kb][3] = packh2(p12, p13);
            ps0 += p00 + p01 + p10 + p11;
            ps1 += p02 + p03 + p12 + p13;
        }
        ps0 += __shfl_xor_sync(0xffffffffu, ps0, 1);
        ps0 += __shfl_xor_sync(0xffffffffu, ps0, 2);
        ps1 += __shfl_xor_sync(0xffffffffu, ps1, 1);
        ps1 += __shfl_xor_sync(0xffffffffu, ps1, 2);
        l0 += ps0; l1 += ps1;

        if (j + 1 < nkt) { CP_WAIT(1); } else { CP_WAIT(0); }
        __syncthreads();

#pragma unroll
        for (int kb = 0; kb < 8; kb++) {
            const int chunk = kb >> 2;
            const int g = (kb & 3) * 2 + (lane >> 4);
#pragma unroll
            for (int np = 0; np < 8; np++) {
                const int br = np * 16 + lr;
                const uint32_t boff = br * 128 + ((g ^ (br & 7)) << 4);
                uint32_t t4[4];
                LDSM_X4(t4, VS + chunk * 16384 + boff);
                uint32_t b0[2] = { t4[0], t4[2] };
                uint32_t b1[2] = { t4[1], t4[3] };
                mma16816_fp(oacc[2*np],   pfrag[kb], b0);
                mma16816_fp(oacc[2*np+1], pfrag[kb], b1);
            }
        }
        __syncthreads();
        if (j + 1 < nkt) { loadV(j + 1); CP_COMMIT(); }
    }

    // ---- writeout: fp16 AO ----
    const float inv0 = 1.f / l0, inv1 = 1.f / l1;
    const int bb = bh >> 4, hh = bh & 15;
    const int rgg0 = qb * 128 + wid * 16 + rloc;
    const size_t base0 = ((size_t)(bb * 2048 + rgg0)) * 2048 + hh * 128;
    const size_t base1 = base0 + (size_t)8 * 2048;
#pragma unroll
    for (int nt = 0; nt < 16; nt++) {
        const int d = nt * 8 + colloc;
        *(__half2*)(g_AOfh + base0 + d) = __floats2half2_rn(oacc[nt][0] * inv0, oacc[nt][1] * inv0);
        *(__half2*)(g_AOfh + base1 + d) = __floats2half2_rn(oacc[nt][2] * inv1, oacc[nt][3] * inv1);
    }
}

// ---------------- launch ----------------
extern "C" void kernel_launch(void* const* d_in, const int* in_sizes, int n_in,
                              void* d_out, int out_size)
{
    (void)in_sizes; (void)n_in; (void)out_size;
    const float* hidden = (const float*)d_in[0];
    const float* q_w = (const float*)d_in[2];
    const float* k_w = (const float*)d_in[3];
    const float* v_w = (const float*)d_in[4];
    const float* o_w = (const float*)d_in[5];
    float* out = (float*)d_out;

    cudaFuncSetAttribute(gemm_mma<1>, cudaFuncAttributeMaxDynamicSharedMemorySize, 196608);
    cudaFuncSetAttribute(gemm_mma<0>, cudaFuncAttributeMaxDynamicSharedMemorySize, 98304);
    cudaFuncSetAttribute(flash_mma, cudaFuncAttributeMaxDynamicSharedMemorySize, FL_SMEM);

    convert_all<<<dim3(8192, 5), 256>>>(hidden, q_w, k_w, v_w, o_w);
    gemm_mma<1><<<dim3(48, 32), 256, 196608>>>(nullptr);
    abar_cam<<<32, 256>>>();
    vt_update<<<4096, 256>>>();
    flash_mma<<<dim3(16, 32), 256, FL_SMEM>>>();
    gemm_mma<0><<<dim3(16, 32), 256, 98304>>>(out);
}

// round 13
// speedup vs baseline: 1.5613x; 1.2691x over previous
#include <cuda_runtime.h>
#include <cuda_bf16.h>
#include <cuda_fp16.h>
#include <math.h>
#include <stdint.h>
#include <float.h>

#define B_  2
#define T_  2048
#define HID_ 2048
#define H_  16
#define D_  128
#define BH_ (B_*H_)
#define BT_ (B_*T_)

// ---------------- device scratch ----------------
__device__ float g_ve[BH_ * D_];
__device__ float g_v1535[BH_ * D_];

// fp16 operands
__device__ __align__(16) __half g_Hfh[(size_t)BT_ * HID_];     // hidden fp16 hi
__device__ __align__(16) __half g_Hfl[(size_t)BT_ * HID_];     // hidden fp16 lo
__device__ __align__(16) __half g_Wfh[3][(size_t)HID_ * HID_]; // qkv weights fp16 (hi only)
__device__ __align__(16) __half g_OWfh[(size_t)HID_ * HID_];   // o_w fp16
__device__ __align__(16) __half g_AOfh[(size_t)BT_ * HID_];    // attn out fp16
__device__ __align__(16) __half g_Qh[(size_t)BH_ * T_ * D_];   // fp16 hi
__device__ __align__(16) __half g_Ql[(size_t)BH_ * T_ * D_];   // fp16 lo (abar only)
__device__ __align__(16) __half g_Kh[(size_t)BH_ * T_ * D_];
__device__ __align__(16) __half g_Kl[(size_t)BH_ * T_ * D_];
__device__ __align__(16) __half g_Vth[(size_t)BH_ * D_ * T_];  // Vt[bh][d][k]

// ---------------- PTX helpers (compute_103-safe) ----------------
__device__ __forceinline__ uint32_t smem_u32(const void* p) {
    uint32_t a;
    asm("{ .reg .u64 t; cvta.to.shared.u64 t, %1; cvt.u32.u64 %0, t; }" : "=r"(a) : "l"(p));
    return a;
}
__device__ __forceinline__ void cp_async16(uint32_t dst, const void* src) {
    asm volatile("cp.async.cg.shared.global [%0], [%1], 16;" :: "r"(dst), "l"(src));
}
#define CP_COMMIT() asm volatile("cp.async.commit_group;" ::: "memory")
#define CP_WAIT(N)  asm volatile("cp.async.wait_group %0;" :: "n"(N) : "memory")

#define LDSM_X4(r, addr) \
    asm volatile("ldmatrix.sync.aligned.m8n8.x4.shared.b16 {%0,%1,%2,%3}, [%4];" \
        : "=r"((r)[0]), "=r"((r)[1]), "=r"((r)[2]), "=r"((r)[3]) : "r"(addr))

__device__ __forceinline__ void mma16816_fp(float* c, const uint32_t* a, const uint32_t* b) {
    asm volatile("mma.sync.aligned.m16n8k16.row.col.f32.f16.f16.f32 "
        "{%0,%1,%2,%3}, {%4,%5,%6,%7}, {%8,%9}, {%0,%1,%2,%3};"
        : "+f"(c[0]), "+f"(c[1]), "+f"(c[2]), "+f"(c[3])
        : "r"(a[0]), "r"(a[1]), "r"(a[2]), "r"(a[3]), "r"(b[0]), "r"(b[1]));
}

__device__ __forceinline__ void split2h(float x, __half& h, __half& l) {
    h = __float2half_rn(x);
    l = __float2half_rn(x - __half2float(h));
}
__device__ __forceinline__ uint32_t packh2(float a, float b) {
    __half2 h = __floats2half2_rn(a, b);
    return *reinterpret_cast<uint32_t*>(&h);
}

// ---------------- input conversions ----------------
// sel 0: hidden -> fp16 hi/lo. sel 1..3: q/k/v weights -> fp16 single. sel 4: o_w -> fp16.
__global__ void convert_all(const float* __restrict__ hs,
                            const float* __restrict__ qw, const float* __restrict__ kw,
                            const float* __restrict__ vw, const float* __restrict__ ow)
{
    const int sel = blockIdx.y;
    if (sel > 0 && blockIdx.x >= 4096) return;
    const size_t i = ((size_t)blockIdx.x * blockDim.x + threadIdx.x) * 4;
    if (sel == 0) {
        const float4 v = *(const float4*)(hs + i);
        __half h0,h1,h2,h3,l0,l1,l2,l3;
        split2h(v.x,h0,l0); split2h(v.y,h1,l1); split2h(v.z,h2,l2); split2h(v.w,h3,l3);
        *(__half2*)(g_Hfh + i)     = __half2(h0, h1);
        *(__half2*)(g_Hfh + i + 2) = __half2(h2, h3);
        *(__half2*)(g_Hfl + i)     = __half2(l0, l1);
        *(__half2*)(g_Hfl + i + 2) = __half2(l2, l3);
        return;
    }
    const float* s = (sel == 1) ? qw : (sel == 2) ? kw : (sel == 3) ? vw : ow;
    __half* dst = (sel == 4) ? g_OWfh : g_Wfh[sel - 1];
    const float4 v = *(const float4*)(s + i);
    *(__half2*)(dst + i)     = __floats2half2_rn(v.x, v.y);
    *(__half2*)(dst + i + 2) = __floats2half2_rn(v.z, v.w);
}

// ---------------- mma.sync GEMM, 3-stage pipeline ----------------
// MODE 1: QKV proj, fp16 2-term (Ah*B + Al*B), grid(48,32): x=(w*16+n).
//         Q/K: rope fused -> fp16 hi/lo. V: fp16 transposed + row-1535 save.
// MODE 0: O proj, fp16 1-term, grid(16,32) -> C (d_out)
#define GT_TILE  16384

template<int MODE>
__global__ void __launch_bounds__(256) gemm_mma(float* __restrict__ C)
{
    constexpr int NT = (MODE == 1) ? 3 : 2;        // tiles per stage
    constexpr uint32_t STAGE = NT * GT_TILE;
    constexpr uint32_t BOFS = (MODE == 1) ? 2u * GT_TILE : 1u * GT_TILE;

    extern __shared__ char smem[];
    const uint32_t sbase = smem_u32(smem);
    const int tid = threadIdx.x;
    const int wid = tid >> 5;
    const int lane = tid & 31;

    int wsel = 0, hsel = 0, mloc, nloc;
    if (MODE == 1) {
        wsel = blockIdx.x >> 4;
        hsel = blockIdx.x & 15;
        mloc = blockIdx.y * 128; nloc = hsel * 128;
    } else {
        mloc = blockIdx.y * 128; nloc = blockIdx.x * 128;
    }

    // loader mapping
    int part, u, rpt;
    if (MODE == 1) {
        if (tid < 64)       { part = 0; u = tid;       rpt = 2; }
        else if (tid < 128) { part = 1; u = tid - 64;  rpt = 2; }
        else                { part = 2; u = tid - 128; rpt = 1; }
    } else {
        part = tid >> 7; u = tid & 127; rpt = 1;
    }
    const char* gsrc;
    if (MODE == 1) {
        gsrc = (part == 0) ? (const char*)g_Hfh : (part == 1) ? (const char*)g_Hfl
                                                : (const char*)g_Wfh[wsel];
    } else {
        gsrc = (part == 0) ? (const char*)g_AOfh : (const char*)g_OWfh;
    }
    const int growbase = (part < NT - 1 || MODE == 0 ? (part == NT - 1 ? nloc : mloc) : nloc);
    const uint32_t tpart = sbase + part * GT_TILE;

    auto load_stage = [&](int c, int s) {
        for (int rr = 0; rr < rpt; rr++) {
            const int r = u * rpt + rr;
            const char* src = gsrc + ((size_t)(growbase + r) * 2048 + c * 64) * 2;
            const uint32_t drow = tpart + s * STAGE + r * 128;
#pragma unroll
            for (int g = 0; g < 8; g++)
                cp_async16(drow + (((g ^ (r & 7)) << 4)), src + g * 16);
        }
    };

    const int wm = wid & 3;
    const int wn = wid >> 2;

    float acc[2][8][4];
#pragma unroll
    for (int a = 0; a < 2; a++)
#pragma unroll
        for (int b = 0; b < 8; b++)
#pragma unroll
            for (int cx = 0; cx < 4; cx++) acc[a][b][cx] = 0.f;

    load_stage(0, 0); CP_COMMIT();
    load_stage(1, 1); CP_COMMIT();

    for (int c = 0; c < 32; ++c) {
        if (c < 31) { CP_WAIT(1); } else { CP_WAIT(0); }
        __syncthreads();
        if (c + 2 < 32) { load_stage(c + 2, (c + 2) % 3); CP_COMMIT(); }

        const uint32_t st = sbase + (c % 3) * STAGE;
#pragma unroll
        for (int ks = 0; ks < 4; ks++) {
            const int lr = lane & 15;
            const int g = ks * 2 + (lane >> 4);

            uint32_t ah[2][4], al[2][4];
#pragma unroll
            for (int mb = 0; mb < 2; mb++) {
                const int r = wm * 32 + mb * 16 + lr;
                const uint32_t off = r * 128 + (((g ^ (r & 7)) << 4));
                LDSM_X4(ah[mb], st + off);
                if (MODE == 1) LDSM_X4(al[mb], st + GT_TILE + off);
            }
            uint32_t bhf[8][2];
#pragma unroll
            for (int np = 0; np < 4; np++) {
                const int r = wn * 64 + np * 16 + lr;
                const uint32_t off = r * 128 + (((g ^ (r & 7)) << 4));
                uint32_t t4[4];
                LDSM_X4(t4, st + BOFS + off);
                bhf[2*np][0] = t4[0]; bhf[2*np][1] = t4[2];
                bhf[2*np+1][0] = t4[1]; bhf[2*np+1][1] = t4[3];
            }
#pragma unroll
            for (int mb = 0; mb < 2; mb++)
#pragma unroll
                for (int nb = 0; nb < 8; nb++) {
                    mma16816_fp(acc[mb][nb], ah[mb], bhf[nb]);
                    if (MODE == 1) mma16816_fp(acc[mb][nb], al[mb], bhf[nb]);
                }
        }
    }

    // ---------------- epilogue ----------------
    if (MODE == 0) {
#pragma unroll
        for (int mb = 0; mb < 2; mb++)
#pragma unroll
            for (int rh = 0; rh < 2; rh++) {
                const int row = wm * 32 + mb * 16 + rh * 8 + (lane >> 2);
                float* dst = C + (size_t)(mloc + row) * 2048 + nloc;
                const int cbase = wn * 64 + (lane & 3) * 2;
#pragma unroll
                for (int nb = 0; nb < 8; nb++)
                    *(float2*)(dst + cbase + nb * 8) =
                        make_float2(acc[mb][nb][rh * 2], acc[mb][nb][rh * 2 + 1]);
            }
    } else {
        __syncthreads();
        float* stg = (float*)smem;     // [128][132]
#pragma unroll
        for (int mb = 0; mb < 2; mb++)
#pragma unroll
            for (int rh = 0; rh < 2; rh++) {
                const int row = wm * 32 + mb * 16 + rh * 8 + (lane >> 2);
                const int cbase = wn * 64 + (lane & 3) * 2;
#pragma unroll
                for (int nb = 0; nb < 8; nb++) {
                    stg[row * 132 + cbase + nb * 8]     = acc[mb][nb][rh * 2];
                    stg[row * 132 + cbase + nb * 8 + 1] = acc[mb][nb][rh * 2 + 1];
                }
            }
        __syncthreads();

        if (wsel == 2) {
            for (int idx = tid; idx < 128 * 128; idx += 256) {
                const int d = idx >> 7, r = idx & 127;
                const int gr = mloc + r;
                const int bb = gr >> 11, t = gr & 2047;
                const float x = stg[r * 132 + d];
                g_Vth[((size_t)((bb * H_ + hsel) * D_ + d)) * T_ + t] = __float2half_rn(x);
                if (t == 1535) g_v1535[(bb * H_ + hsel) * 128 + d] = x;
            }
        } else {
            __half* Oh = (wsel == 0) ? g_Qh : g_Kh;
            __half* Ol = (wsel == 0) ? g_Ql : g_Kl;
            for (int idx = tid; idx < 128 * 64; idx += 256) {
                const int r = idx >> 6, j = idx & 63;
                const int gr = mloc + r;
                const int bb = gr >> 11, t = gr & 2047;
                const float inv = powf(10000.f, -(float)j * (1.f / 64.f));
                float s, cc;
                sincosf((float)t * inv, &s, &cc);
                const float x1 = stg[r * 132 + j];
                const float x2 = stg[r * 132 + j + 64];
                const float y1 = x1 * cc - x2 * s;
                const float y2 = x2 * cc + x1 * s;
                const size_t base = (((size_t)(bb * H_ + hsel) * T_ + t) << 7);
                __half h, l;
                split2h(y1, h, l); Oh[base + j] = h;      Ol[base + j] = l;
                split2h(y2, h, l); Oh[base + j + 64] = h; Ol[base + j + 64] = l;
            }
        }
    }
}

// ---------------- A_bar softmax + CAM bernoulli -> g_ve ----------------
__device__ __forceinline__ uint32_t rotl32(uint32_t x, int r) { return (x << r) | (x >> (32 - r)); }

__global__ void __launch_bounds__(256) abar_cam()
{
    const int bh = blockIdx.x;
    __shared__ float qrow[128];
    __shared__ float sc[2048];
    __shared__ float red[256];
    __shared__ float maskf;
    const int tid = threadIdx.x;

    const size_t qoff = ((size_t)bh * T_ + (T_ - 1)) * 128;
    if (tid < 128)
        qrow[tid] = __half2float(g_Qh[qoff + tid]) + __half2float(g_Ql[qoff + tid]);
    __syncthreads();

    for (int k = tid; k < 2048; k += 256) {
        const size_t koff = ((size_t)bh * T_ + k) * 128;
        const __half2* kh = (const __half2*)(g_Kh + koff);
        const __half2* kl = (const __half2*)(g_Kl + koff);
        float s = 0.f;
#pragma unroll
        for (int i = 0; i < 64; i++) {
            const float2 a = __half22float2(kh[i]);
            const float2 b = __half22float2(kl[i]);
            s = fmaf(a.x + b.x, qrow[2 * i], s);
            s = fmaf(a.y + b.y, qrow[2 * i + 1], s);
        }
        sc[k] = s * 0.08838834764831845f;
    }
    __syncthreads();

    float m = -FLT_MAX;
    for (int k = tid; k < 2048; k += 256) m = fmaxf(m, sc[k]);
    red[tid] = m; __syncthreads();
    for (int o = 128; o > 0; o >>= 1) { if (tid < o) red[tid] = fmaxf(red[tid], red[tid + o]); __syncthreads(); }
    const float gm = red[0];
    __syncthreads();

    float sum = 0.f;
    for (int k = tid; k < 2048; k += 256) { const float p = expf(sc[k] - gm); sc[k] = p; sum += p; }
    red[tid] = sum; __syncthreads();
    for (int o = 128; o > 0; o >>= 1) { if (tid < o) red[tid] += red[tid + o]; __syncthreads(); }
    const float invs = 1.f / red[0];
    __syncthreads();

    for (int k = tid; k < 2048; k += 256) sc[k] *= invs;
    __syncthreads();

    float ws = 0.f;
    for (int k = 1536 + tid; k < 2048; k += 256) ws += sc[k];
    red[tid] = ws; __syncthreads();
    for (int o = 128; o > 0; o >>= 1) { if (tid < o) red[tid] += red[tid + o]; __syncthreads(); }

    if (tid == 0) {
        const float avg = fmaxf(red[0] * (1.f / 512.f), 1e-6f);
        float p = fminf(fmaxf(sc[1535] / avg, 0.f), 1.f);
        uint32_t x0 = 0u, x1 = (uint32_t)bh;
        const uint32_t k0 = 0u, k1 = 42u, k2 = 0x1BD11BDAu ^ k0 ^ k1;
        x0 += k0; x1 += k1;
#define TF4(a,b,c,d)  x0+=x1; x1=rotl32(x1,a); x1^=x0; \
                      x0+=x1; x1=rotl32(x1,b); x1^=x0; \
                      x0+=x1; x1=rotl32(x1,c); x1^=x0; \
                      x0+=x1; x1=rotl32(x1,d); x1^=x0;
        TF4(13,15,26,6)   x0 += k1; x1 += k2 + 1u;
        TF4(17,29,16,24)  x0 += k2; x1 += k0 + 2u;
        TF4(13,15,26,6)   x0 += k0; x1 += k1 + 3u;
        TF4(17,29,16,24)  x0 += k1; x1 += k2 + 4u;
        TF4(13,15,26,6)   x0 += k2; x1 += k0 + 5u;
#undef TF4
        const uint32_t bits = x0 ^ x1;
        float uu = __uint_as_float((bits >> 9) | 0x3f800000u) - 1.0f;
        uu = fmaxf(uu, 0.f);
        maskf = (uu < p) ? 1.f : 0.f;
    }
    __syncthreads();

    if (tid < 128)
        g_ve[bh * 128 + tid] = g_v1535[bh * 128 + tid] * maskf * (1.f / 512.f);
}

// CAM window update in-place on fp16 Vt
__global__ void vt_update()
{
    const int idx = blockIdx.x * blockDim.x + threadIdx.x;
    const int bh = idx >> 15;
    const int rem = idx & 32767;
    const int d = rem >> 8;
    const int kk = rem & 255;
    const float ve = g_ve[bh * 128 + d];
    __half2* p = (__half2*)(g_Vth + ((size_t)(bh * 128 + d)) * 2048 + 1536) + kk;
    float2 x = __half22float2(*p);
    *p = __floats2half2_rn(x.x + ve, x.y + ve);
}

// ---------------- fused flash attention (fp16 S + fp16 PV) ----------------
#define FL_SMEM 131072

__global__ void __launch_bounds__(256) flash_mma()
{
    extern __shared__ char smem[];
    const uint32_t sb = smem_u32(smem);
    const uint32_t QS = sb, KS = sb + 32768, VS = sb + 98304;
    const int tid = threadIdx.x, wid = tid >> 5, lane = tid & 31;
    const int bh = blockIdx.y;
    const int qb = 15 - blockIdx.x;
    const int nkt = qb + 1;

    {
        const int c = tid >> 7, r = tid & 127;
        const char* sp = (const char*)(g_Qh + ((size_t)(bh * 2048 + qb * 128 + r)) * 128 + c * 64);
        const uint32_t drow = QS + c * 16384 + r * 128;
#pragma unroll
        for (int g = 0; g < 8; g++) cp_async16(drow + ((g ^ (r & 7)) << 4), sp + g * 16);
    }
    CP_COMMIT();

    auto loadK = [&](int j, int s) {
        const int c = tid >> 7, r = tid & 127;
        const char* sp = (const char*)(g_Kh + ((size_t)(bh * 2048 + j * 128 + r)) * 128 + c * 64);
        const uint32_t drow = KS + s * 32768 + c * 16384 + r * 128;
#pragma unroll
        for (int g = 0; g < 8; g++) cp_async16(drow + ((g ^ (r & 7)) << 4), sp + g * 16);
    };
    auto loadV = [&](int j) {
        const int c = tid >> 7, r = tid & 127;
        const char* sp = (const char*)(g_Vth + ((size_t)(bh * 128 + r)) * 2048 + j * 128 + c * 64);
        const uint32_t drow = VS + c * 16384 + r * 128;
#pragma unroll
        for (int g = 0; g < 8; g++) cp_async16(drow + ((g ^ (r & 7)) << 4), sp + g * 16);
    };

    loadK(0, 0); CP_COMMIT();
    loadV(0);    CP_COMMIT();

    float oacc[16][4];
#pragma unroll
    for (int nt = 0; nt < 16; nt++)
#pragma unroll
        for (int e = 0; e < 4; e++) oacc[nt][e] = 0.f;
    float m0 = -1e30f, m1 = -1e30f, l0 = 0.f, l1 = 0.f;
    uint32_t pfrag[8][4];

    const float scale = 0.08838834764831845f;
    const int lr = lane & 15;
    const int rloc = (lane >> 2);
    const int colloc = (lane & 3) * 2;

    for (int j = 0; j < nkt; j++) {
        const int sK = j & 1;
        CP_WAIT(1);
        __syncthreads();
        if (j + 1 < nkt) { loadK(j + 1, sK ^ 1); CP_COMMIT(); }

        float sacc[16][4];
#pragma unroll
        for (int nt = 0; nt < 16; nt++)
#pragma unroll
            for (int e = 0; e < 4; e++) sacc[nt][e] = 0.f;

        const uint32_t kst = KS + sK * 32768;
#pragma unroll
        for (int ks = 0; ks < 8; ks++) {
            const int chunk = ks >> 2;
            const int g = (ks & 3) * 2 + (lane >> 4);
            const int ar = wid * 16 + lr;
            const uint32_t aoff = ar * 128 + ((g ^ (ar & 7)) << 4);
            uint32_t ah[4];
            LDSM_X4(ah, QS + chunk * 16384 + aoff);
#pragma unroll
            for (int np = 0; np < 8; np++) {
                const int br = np * 16 + lr;
                const uint32_t boff = br * 128 + ((g ^ (br & 7)) << 4);
                uint32_t t4[4];
                LDSM_X4(t4, kst + chunk * 16384 + boff);
                uint32_t b0[2] = { t4[0], t4[2] };
                uint32_t b1[2] = { t4[1], t4[3] };
                mma16816_fp(sacc[2*np],   ah, b0);
                mma16816_fp(sacc[2*np+1], ah, b1);
            }
        }

        const bool diag = (j == qb);
        const int rg0 = wid * 16 + rloc;
#pragma unroll
        for (int nt = 0; nt < 16; nt++) {
            float* s = sacc[nt];
            s[0] *= scale; s[1] *= scale; s[2] *= scale; s[3] *= scale;
            if (diag) {
                const int cl = nt * 8 + colloc;
                if (cl     > rg0)     s[0] = -1e30f;
                if (cl + 1 > rg0)     s[1] = -1e30f;
                if (cl     > rg0 + 8) s[2] = -1e30f;
                if (cl + 1 > rg0 + 8) s[3] = -1e30f;
            }
        }

        float mx0 = -1e30f, mx1 = -1e30f;
#pragma unroll
        for (int nt = 0; nt < 16; nt++) {
            mx0 = fmaxf(mx0, fmaxf(sacc[nt][0], sacc[nt][1]));
            mx1 = fmaxf(mx1, fmaxf(sacc[nt][2], sacc[nt][3]));
        }
        mx0 = fmaxf(mx0, __shfl_xor_sync(0xffffffffu, mx0, 1));
        mx0 = fmaxf(mx0, __shfl_xor_sync(0xffffffffu, mx0, 2));
        mx1 = fmaxf(mx1, __shfl_xor_sync(0xffffffffu, mx1, 1));
        mx1 = fmaxf(mx1, __shfl_xor_sync(0xffffffffu, mx1, 2));
        const float mn0 = fmaxf(m0, mx0), mn1 = fmaxf(m1, mx1);
        const float cr0 = __expf(m0 - mn0), cr1 = __expf(m1 - mn1);
        l0 *= cr0; l1 *= cr1; m0 = mn0; m1 = mn1;
#pragma unroll
        for (int nt = 0; nt < 16; nt++) {
            oacc[nt][0] *= cr0; oacc[nt][1] *= cr0;
            oacc[nt][2] *= cr1; oacc[nt][3] *= cr1;
        }
        float ps0 = 0.f, ps1 = 0.f;
#pragma unroll
        for (int kb = 0; kb < 8; kb++) {
            const float p00 = __expf(sacc[2*kb][0]   - mn0), p01 = __expf(sacc[2*kb][1]   - mn0);
            const float p02 = __expf(sacc[2*kb][2]   - mn1), p03 = __expf(sacc[2*kb][3]   - mn1);
            const float p10 = __expf(sacc[2*kb+1][0] - mn0), p11 = __expf(sacc[2*kb+1][1] - mn0);
            const float p12 = __expf(sacc[2*kb+1][2] - mn1), p13 = __expf(sacc[2*kb+1][3] - mn1);
            pfrag[kb][0] = packh2(p00, p01);
            pfrag[kb][1] = packh2(p02, p03);
            pfrag[kb][2] = packh2(p10, p11);
            pfrag[kb][3] = packh2(p12, p13);
            ps0 += p00 + p01 + p10 + p11;
            ps1 += p02 + p03 + p12 + p13;
        }
        ps0 += __shfl_xor_sync(0xffffffffu, ps0, 1);
        ps0 += __shfl_xor_sync(0xffffffffu, ps0, 2);
        ps1 += __shfl_xor_sync(0xffffffffu, ps1, 1);
        ps1 += __shfl_xor_sync(0xffffffffu, ps1, 2);
        l0 += ps0; l1 += ps1;

        if (j + 1 < nkt) { CP_WAIT(1); } else { CP_WAIT(0); }
        __syncthreads();

#pragma unroll
        for (int kb = 0; kb < 8; kb++) {
            const int chunk = kb >> 2;
            const int g = (kb & 3) * 2 + (lane >> 4);
#pragma unroll
            for (int np = 0; np < 8; np++) {
                const int br = np * 16 + lr;
                const uint32_t boff = br * 128 + ((g ^ (br & 7)) << 4);
                uint32_t t4[4];
                LDSM_X4(t4, VS + chunk * 16384 + boff);
                uint32_t b0[2] = { t4[0], t4[2] };
                uint32_t b1[2] = { t4[1], t4[3] };
                mma16816_fp(oacc[2*np],   pfrag[kb], b0);
                mma16816_fp(oacc[2*np+1], pfrag[kb], b1);
            }
        }
        __syncthreads();
        if (j + 1 < nkt) { loadV(j + 1); CP_COMMIT(); }
    }

    // ---- writeout: fp16 AO ----
    const float inv0 = 1.f / l0, inv1 = 1.f / l1;
    const int bb = bh >> 4, hh = bh & 15;
    const int rgg0 = qb * 128 + wid * 16 + rloc;
    const size_t base0 = ((size_t)(bb * 2048 + rgg0)) * 2048 + hh * 128;
    const size_t base1 = base0 + (size_t)8 * 2048;
#pragma unroll
    for (int nt = 0; nt < 16; nt++) {
        const int d = nt * 8 + colloc;
        *(__half2*)(g_AOfh + base0 + d) = __floats2half2_rn(oacc[nt][0] * inv0, oacc[nt][1] * inv0);
        *(__half2*)(g_AOfh + base1 + d) = __floats2half2_rn(oacc[nt][2] * inv1, oacc[nt][3] * inv1);
    }
}

// ---------------- launch ----------------
extern "C" void kernel_launch(void* const* d_in, const int* in_sizes, int n_in,
                              void* d_out, int out_size)
{
    (void)in_sizes; (void)n_in; (void)out_size;
    const float* hidden = (const float*)d_in[0];
    const float* q_w = (const float*)d_in[2];
    const float* k_w = (const float*)d_in[3];
    const float* v_w = (const float*)d_in[4];
    const float* o_w = (const float*)d_in[5];
    float* out = (float*)d_out;

    cudaFuncSetAttribute(gemm_mma<1>, cudaFuncAttributeMaxDynamicSharedMemorySize, 147456);
    cudaFuncSetAttribute(gemm_mma<0>, cudaFuncAttributeMaxDynamicSharedMemorySize, 98304);
    cudaFuncSetAttribute(flash_mma, cudaFuncAttributeMaxDynamicSharedMemorySize, FL_SMEM);

    convert_all<<<dim3(8192, 5), 256>>>(hidden, q_w, k_w, v_w, o_w);
    gemm_mma<1><<<dim3(48, 32), 256, 147456>>>(nullptr);
    abar_cam<<<32, 256>>>();
    vt_update<<<4096, 256>>>();
    flash_mma<<<dim3(16, 32), 256, FL_SMEM>>>();
    gemm_mma<0><<<dim3(16, 32), 256, 98304>>>(out);
}

// round 14
// speedup vs baseline: 2.2382x; 1.4335x over previous
#include <cuda_runtime.h>
#include <cuda_bf16.h>
#include <cuda_fp16.h>
#include <math.h>
#include <stdint.h>
#include <float.h>

#define B_  2
#define T_  2048
#define HID_ 2048
#define H_  16
#define D_  128
#define BH_ (B_*H_)
#define BT_ (B_*T_)

// ---------------- device scratch ----------------
__device__ float g_ve[BH_ * D_];
__device__ float g_v1535[BH_ * D_];

// fp16 operands
__device__ __align__(16) __half g_Hfh[(size_t)BT_ * HID_];     // hidden fp16
__device__ __align__(16) __half g_Wfh[3][(size_t)HID_ * HID_]; // qkv weights fp16
__device__ __align__(16) __half g_OWfh[(size_t)HID_ * HID_];   // o_w fp16
__device__ __align__(16) __half g_AOfh[(size_t)BT_ * HID_];    // attn out fp16
__device__ __align__(16) __half g_Qh[(size_t)BH_ * T_ * D_];   // fp16 hi
__device__ __align__(16) __half g_Ql[(size_t)BH_ * T_ * D_];   // fp16 lo (abar only)
__device__ __align__(16) __half g_Kh[(size_t)BH_ * T_ * D_];
__device__ __align__(16) __half g_Kl[(size_t)BH_ * T_ * D_];
__device__ __align__(16) __half g_Vth[(size_t)BH_ * D_ * T_];  // Vt[bh][d][k]

// ---------------- PTX helpers (compute_103-safe) ----------------
__device__ __forceinline__ uint32_t smem_u32(const void* p) {
    uint32_t a;
    asm("{ .reg .u64 t; cvta.to.shared.u64 t, %1; cvt.u32.u64 %0, t; }" : "=r"(a) : "l"(p));
    return a;
}
__device__ __forceinline__ void cp_async16(uint32_t dst, const void* src) {
    asm volatile("cp.async.cg.shared.global [%0], [%1], 16;" :: "r"(dst), "l"(src));
}
#define CP_COMMIT() asm volatile("cp.async.commit_group;" ::: "memory")
#define CP_WAIT(N)  asm volatile("cp.async.wait_group %0;" :: "n"(N) : "memory")

#define LDSM_X4(r, addr) \
    asm volatile("ldmatrix.sync.aligned.m8n8.x4.shared.b16 {%0,%1,%2,%3}, [%4];" \
        : "=r"((r)[0]), "=r"((r)[1]), "=r"((r)[2]), "=r"((r)[3]) : "r"(addr))

__device__ __forceinline__ void mma16816_fp(float* c, const uint32_t* a, const uint32_t* b) {
    asm volatile("mma.sync.aligned.m16n8k16.row.col.f32.f16.f16.f32 "
        "{%0,%1,%2,%3}, {%4,%5,%6,%7}, {%8,%9}, {%0,%1,%2,%3};"
        : "+f"(c[0]), "+f"(c[1]), "+f"(c[2]), "+f"(c[3])
        : "r"(a[0]), "r"(a[1]), "r"(a[2]), "r"(a[3]), "r"(b[0]), "r"(b[1]));
}

__device__ __forceinline__ void split2h(float x, __half& h, __half& l) {
    h = __float2half_rn(x);
    l = __float2half_rn(x - __half2float(h));
}
__device__ __forceinline__ uint32_t packh2(float a, float b) {
    __half2 h = __floats2half2_rn(a, b);
    return *reinterpret_cast<uint32_t*>(&h);
}

// ---------------- input conversions: all fp16 single ----------------
__global__ void convert_all(const float* __restrict__ hs,
                            const float* __restrict__ qw, const float* __restrict__ kw,
                            const float* __restrict__ vw, const float* __restrict__ ow)
{
    const int sel = blockIdx.y;
    if (sel > 0 && blockIdx.x >= 4096) return;
    const size_t i = ((size_t)blockIdx.x * blockDim.x + threadIdx.x) * 4;
    const float* s = (sel == 0) ? hs : (sel == 1) ? qw : (sel == 2) ? kw : (sel == 3) ? vw : ow;
    __half* dst = (sel == 0) ? g_Hfh : (sel == 4) ? g_OWfh : g_Wfh[sel - 1];
    const float4 v = *(const float4*)(s + i);
    *(__half2*)(dst + i)     = __floats2half2_rn(v.x, v.y);
    *(__half2*)(dst + i + 2) = __floats2half2_rn(v.z, v.w);
}

// ---------------- mma.sync fp16 GEMM, 3-stage pipeline ----------------
// MODE 1: QKV proj grid(48,32): x=(w*16+n). Q/K: rope fused -> fp16 hi/lo.
//         V: fp16 transposed + row-1535 save.
// MODE 0: O proj grid(16,32) -> C (d_out)
#define GT_TILE  16384
#define GT_STAGE (2 * GT_TILE)     // 32KB per stage (A, B)
#define GT_SMEM  (3 * GT_STAGE)    // 96KB

template<int MODE>
__global__ void __launch_bounds__(256) gemm_mma(float* __restrict__ C)
{
    extern __shared__ char smem[];
    const uint32_t sbase = smem_u32(smem);
    const int tid = threadIdx.x;
    const int wid = tid >> 5;
    const int lane = tid & 31;

    int wsel = 0, hsel = 0, mloc, nloc;
    if (MODE == 1) {
        wsel = blockIdx.x >> 4;
        hsel = blockIdx.x & 15;
        mloc = blockIdx.y * 128; nloc = hsel * 128;
    } else {
        mloc = blockIdx.y * 128; nloc = blockIdx.x * 128;
    }

    const int part = tid >> 7;          // 0 = A, 1 = B
    const int u = tid & 127;
    const char* gsrc;
    if (MODE == 1) gsrc = (part == 0) ? (const char*)g_Hfh : (const char*)g_Wfh[wsel];
    else           gsrc = (part == 0) ? (const char*)g_AOfh : (const char*)g_OWfh;
    const int growbase = (part == 0) ? mloc : nloc;
    const uint32_t tpart = sbase + part * GT_TILE;

    auto load_stage = [&](int c, int s) {
        const int r = u;
        const char* src = gsrc + ((size_t)(growbase + r) * 2048 + c * 64) * 2;
        const uint32_t drow = tpart + s * GT_STAGE + r * 128;
#pragma unroll
        for (int g = 0; g < 8; g++)
            cp_async16(drow + (((g ^ (r & 7)) << 4)), src + g * 16);
    };

    const int wm = wid & 3;
    const int wn = wid >> 2;

    float acc[2][8][4];
#pragma unroll
    for (int a = 0; a < 2; a++)
#pragma unroll
        for (int b = 0; b < 8; b++)
#pragma unroll
            for (int cx = 0; cx < 4; cx++) acc[a][b][cx] = 0.f;

    load_stage(0, 0); CP_COMMIT();
    load_stage(1, 1); CP_COMMIT();

    for (int c = 0; c < 32; ++c) {
        if (c < 31) { CP_WAIT(1); } else { CP_WAIT(0); }
        __syncthreads();
        if (c + 2 < 32) { load_stage(c + 2, (c + 2) % 3); CP_COMMIT(); }

        const uint32_t st = sbase + (c % 3) * GT_STAGE;
#pragma unroll
        for (int ks = 0; ks < 4; ks++) {
            const int lr = lane & 15;
            const int g = ks * 2 + (lane >> 4);

            uint32_t ah[2][4];
#pragma unroll
            for (int mb = 0; mb < 2; mb++) {
                const int r = wm * 32 + mb * 16 + lr;
                const uint32_t off = r * 128 + (((g ^ (r & 7)) << 4));
                LDSM_X4(ah[mb], st + off);
            }
            uint32_t bhf[8][2];
#pragma unroll
            for (int np = 0; np < 4; np++) {
                const int r = wn * 64 + np * 16 + lr;
                const uint32_t off = r * 128 + (((g ^ (r & 7)) << 4));
                uint32_t t4[4];
                LDSM_X4(t4, st + GT_TILE + off);
                bhf[2*np][0] = t4[0]; bhf[2*np][1] = t4[2];
                bhf[2*np+1][0] = t4[1]; bhf[2*np+1][1] = t4[3];
            }
#pragma unroll
            for (int mb = 0; mb < 2; mb++)
#pragma unroll
                for (int nb = 0; nb < 8; nb++)
                    mma16816_fp(acc[mb][nb], ah[mb], bhf[nb]);
        }
    }

    // ---------------- epilogue ----------------
    if (MODE == 0) {
#pragma unroll
        for (int mb = 0; mb < 2; mb++)
#pragma unroll
            for (int rh = 0; rh < 2; rh++) {
                const int row = wm * 32 + mb * 16 + rh * 8 + (lane >> 2);
                float* dst = C + (size_t)(mloc + row) * 2048 + nloc;
                const int cbase = wn * 64 + (lane & 3) * 2;
#pragma unroll
                for (int nb = 0; nb < 8; nb++)
                    *(float2*)(dst + cbase + nb * 8) =
                        make_float2(acc[mb][nb][rh * 2], acc[mb][nb][rh * 2 + 1]);
            }
    } else {
        __syncthreads();
        float* stg = (float*)smem;     // [128][132]
#pragma unroll
        for (int mb = 0; mb < 2; mb++)
#pragma unroll
            for (int rh = 0; rh < 2; rh++) {
                const int row = wm * 32 + mb * 16 + rh * 8 + (lane >> 2);
                const int cbase = wn * 64 + (lane & 3) * 2;
#pragma unroll
                for (int nb = 0; nb < 8; nb++) {
                    stg[row * 132 + cbase + nb * 8]     = acc[mb][nb][rh * 2];
                    stg[row * 132 + cbase + nb * 8 + 1] = acc[mb][nb][rh * 2 + 1];
                }
            }
        __syncthreads();

        if (wsel == 2) {
            for (int idx = tid; idx < 128 * 128; idx += 256) {
                const int d = idx >> 7, r = idx & 127;
                const int gr = mloc + r;
                const int bb = gr >> 11, t = gr & 2047;
                const float x = stg[r * 132 + d];
                g_Vth[((size_t)((bb * H_ + hsel) * D_ + d)) * T_ + t] = __float2half_rn(x);
                if (t == 1535) g_v1535[(bb * H_ + hsel) * 128 + d] = x;
            }
        } else {
            __half* Oh = (wsel == 0) ? g_Qh : g_Kh;
            __half* Ol = (wsel == 0) ? g_Ql : g_Kl;
            for (int idx = tid; idx < 128 * 64; idx += 256) {
                const int r = idx >> 6, j = idx & 63;
                const int gr = mloc + r;
                const int bb = gr >> 11, t = gr & 2047;
                const float inv = powf(10000.f, -(float)j * (1.f / 64.f));
                float s, cc;
                sincosf((float)t * inv, &s, &cc);
                const float x1 = stg[r * 132 + j];
                const float x2 = stg[r * 132 + j + 64];
                const float y1 = x1 * cc - x2 * s;
                const float y2 = x2 * cc + x1 * s;
                const size_t base = (((size_t)(bb * H_ + hsel) * T_ + t) << 7);
                __half h, l;
                split2h(y1, h, l); Oh[base + j] = h;      Ol[base + j] = l;
                split2h(y2, h, l); Oh[base + j + 64] = h; Ol[base + j + 64] = l;
            }
        }
    }
}

// ---------------- A_bar softmax + CAM bernoulli -> g_ve ----------------
__device__ __forceinline__ uint32_t rotl32(uint32_t x, int r) { return (x << r) | (x >> (32 - r)); }

__global__ void __launch_bounds__(256) abar_cam()
{
    const int bh = blockIdx.x;
    __shared__ float qrow[128];
    __shared__ float sc[2048];
    __shared__ float red[256];
    __shared__ float maskf;
    const int tid = threadIdx.x;

    const size_t qoff = ((size_t)bh * T_ + (T_ - 1)) * 128;
    if (tid < 128)
        qrow[tid] = __half2float(g_Qh[qoff + tid]) + __half2float(g_Ql[qoff + tid]);
    __syncthreads();

    for (int k = tid; k < 2048; k += 256) {
        const size_t koff = ((size_t)bh * T_ + k) * 128;
        const __half2* kh = (const __half2*)(g_Kh + koff);
        const __half2* kl = (const __half2*)(g_Kl + koff);
        float s = 0.f;
#pragma unroll
        for (int i = 0; i < 64; i++) {
            const float2 a = __half22float2(kh[i]);
            const float2 b = __half22float2(kl[i]);
            s = fmaf(a.x + b.x, qrow[2 * i], s);
            s = fmaf(a.y + b.y, qrow[2 * i + 1], s);
        }
        sc[k] = s * 0.08838834764831845f;
    }
    __syncthreads();

    float m = -FLT_MAX;
    for (int k = tid; k < 2048; k += 256) m = fmaxf(m, sc[k]);
    red[tid] = m; __syncthreads();
    for (int o = 128; o > 0; o >>= 1) { if (tid < o) red[tid] = fmaxf(red[tid], red[tid + o]); __syncthreads(); }
    const float gm = red[0];
    __syncthreads();

    float sum = 0.f;
    for (int k = tid; k < 2048; k += 256) { const float p = expf(sc[k] - gm); sc[k] = p; sum += p; }
    red[tid] = sum; __syncthreads();
    for (int o = 128; o > 0; o >>= 1) { if (tid < o) red[tid] += red[tid + o]; __syncthreads(); }
    const float invs = 1.f / red[0];
    __syncthreads();

    for (int k = tid; k < 2048; k += 256) sc[k] *= invs;
    __syncthreads();

    float ws = 0.f;
    for (int k = 1536 + tid; k < 2048; k += 256) ws += sc[k];
    red[tid] = ws; __syncthreads();
    for (int o = 128; o > 0; o >>= 1) { if (tid < o) red[tid] += red[tid + o]; __syncthreads(); }

    if (tid == 0) {
        const float avg = fmaxf(red[0] * (1.f / 512.f), 1e-6f);
        float p = fminf(fmaxf(sc[1535] / avg, 0.f), 1.f);
        uint32_t x0 = 0u, x1 = (uint32_t)bh;
        const uint32_t k0 = 0u, k1 = 42u, k2 = 0x1BD11BDAu ^ k0 ^ k1;
        x0 += k0; x1 += k1;
#define TF4(a,b,c,d)  x0+=x1; x1=rotl32(x1,a); x1^=x0; \
                      x0+=x1; x1=rotl32(x1,b); x1^=x0; \
                      x0+=x1; x1=rotl32(x1,c); x1^=x0; \
                      x0+=x1; x1=rotl32(x1,d); x1^=x0;
        TF4(13,15,26,6)   x0 += k1; x1 += k2 + 1u;
        TF4(17,29,16,24)  x0 += k2; x1 += k0 + 2u;
        TF4(13,15,26,6)   x0 += k0; x1 += k1 + 3u;
        TF4(17,29,16,24)  x0 += k1; x1 += k2 + 4u;
        TF4(13,15,26,6)   x0 += k2; x1 += k0 + 5u;
#undef TF4
        const uint32_t bits = x0 ^ x1;
        float uu = __uint_as_float((bits >> 9) | 0x3f800000u) - 1.0f;
        uu = fmaxf(uu, 0.f);
        maskf = (uu < p) ? 1.f : 0.f;
    }
    __syncthreads();

    if (tid < 128)
        g_ve[bh * 128 + tid] = g_v1535[bh * 128 + tid] * maskf * (1.f / 512.f);
}

// CAM window update in-place on fp16 Vt
__global__ void vt_update()
{
    const int idx = blockIdx.x * blockDim.x + threadIdx.x;
    const int bh = idx >> 15;
    const int rem = idx & 32767;
    const int d = rem >> 8;
    const int kk = rem & 255;
    const float ve = g_ve[bh * 128 + d];
    __half2* p = (__half2*)(g_Vth + ((size_t)(bh * 128 + d)) * 2048 + 1536) + kk;
    float2 x = __half22float2(*p);
    *p = __floats2half2_rn(x.x + ve, x.y + ve);
}

// ---------------- fused flash attention (fp16 S + fp16 PV) ----------------
#define FL_SMEM 131072

__global__ void __launch_bounds__(256) flash_mma()
{
    extern __shared__ char smem[];
    const uint32_t sb = smem_u32(smem);
    const uint32_t QS = sb, KS = sb + 32768, VS = sb + 98304;
    const int tid = threadIdx.x, wid = tid >> 5, lane = tid & 31;
    const int bh = blockIdx.y;
    const int qb = 15 - blockIdx.x;
    const int nkt = qb + 1;

    {
        const int c = tid >> 7, r = tid & 127;
        const char* sp = (const char*)(g_Qh + ((size_t)(bh * 2048 + qb * 128 + r)) * 128 + c * 64);
        const uint32_t drow = QS + c * 16384 + r * 128;
#pragma unroll
        for (int g = 0; g < 8; g++) cp_async16(drow + ((g ^ (r & 7)) << 4), sp + g * 16);
    }
    CP_COMMIT();

    auto loadK = [&](int j, int s) {
        const int c = tid >> 7, r = tid & 127;
        const char* sp = (const char*)(g_Kh + ((size_t)(bh * 2048 + j * 128 + r)) * 128 + c * 64);
        const uint32_t drow = KS + s * 32768 + c * 16384 + r * 128;
#pragma unroll
        for (int g = 0; g < 8; g++) cp_async16(drow + ((g ^ (r & 7)) << 4), sp + g * 16);
    };
    auto loadV = [&](int j) {
        const int c = tid >> 7, r = tid & 127;
        const char* sp = (const char*)(g_Vth + ((size_t)(bh * 128 + r)) * 2048 + j * 128 + c * 64);
        const uint32_t drow = VS + c * 16384 + r * 128;
#pragma unroll
        for (int g = 0; g < 8; g++) cp_async16(drow + ((g ^ (r & 7)) << 4), sp + g * 16);
    };

    loadK(0, 0); CP_COMMIT();
    loadV(0);    CP_COMMIT();

    float oacc[16][4];
#pragma unroll
    for (int nt = 0; nt < 16; nt++)
#pragma unroll
        for (int e = 0; e < 4; e++) oacc[nt][e] = 0.f;
    float m0 = -1e30f, m1 = -1e30f, l0 = 0.f, l1 = 0.f;
    uint32_t pfrag[8][4];

    const float scale = 0.08838834764831845f;
    const int lr = lane & 15;
    const int rloc = (lane >> 2);
    const int colloc = (lane & 3) * 2;

    for (int j = 0; j < nkt; j++) {
        const int sK = j & 1;
        CP_WAIT(1);
        __syncthreads();
        if (j + 1 < nkt) { loadK(j + 1, sK ^ 1); CP_COMMIT(); }

        float sacc[16][4];
#pragma unroll
        for (int nt = 0; nt < 16; nt++)
#pragma unroll
            for (int e = 0; e < 4; e++) sacc[nt][e] = 0.f;

        const uint32_t kst = KS + sK * 32768;
#pragma unroll
        for (int ks = 0; ks < 8; ks++) {
            const int chunk = ks >> 2;
            const int g = (ks & 3) * 2 + (lane >> 4);
            const int ar = wid * 16 + lr;
            const uint32_t aoff = ar * 128 + ((g ^ (ar & 7)) << 4);
            uint32_t ah[4];
            LDSM_X4(ah, QS + chunk * 16384 + aoff);
#pragma unroll
            for (int np = 0; np < 8; np++) {
                const int br = np * 16 + lr;
                const uint32_t boff = br * 128 + ((g ^ (br & 7)) << 4);
                uint32_t t4[4];
                LDSM_X4(t4, kst + chunk * 16384 + boff);
                uint32_t b0[2] = { t4[0], t4[2] };
                uint32_t b1[2] = { t4[1], t4[3] };
                mma16816_fp(sacc[2*np],   ah, b0);
                mma16816_fp(sacc[2*np+1], ah, b1);
            }
        }

        const bool diag = (j == qb);
        const int rg0 = wid * 16 + rloc;
#pragma unroll
        for (int nt = 0; nt < 16; nt++) {
            float* s = sacc[nt];
            s[0] *= scale; s[1] *= scale; s[2] *= scale; s[3] *= scale;
            if (diag) {
                const int cl = nt * 8 + colloc;
                if (cl     > rg0)     s[0] = -1e30f;
                if (cl + 1 > rg0)     s[1] = -1e30f;
                if (cl     > rg0 + 8) s[2] = -1e30f;
                if (cl + 1 > rg0 + 8) s[3] = -1e30f;
            }
        }

        float mx0 = -1e30f, mx1 = -1e30f;
#pragma unroll
        for (int nt = 0; nt < 16; nt++) {
            mx0 = fmaxf(mx0, fmaxf(sacc[nt][0], sacc[nt][1]));
            mx1 = fmaxf(mx1, fmaxf(sacc[nt][2], sacc[nt][3]));
        }
        mx0 = fmaxf(mx0, __shfl_xor_sync(0xffffffffu, mx0, 1));
        mx0 = fmaxf(mx0, __shfl_xor_sync(0xffffffffu, mx0, 2));
        mx1 = fmaxf(mx1, __shfl_xor_sync(0xffffffffu, mx1, 1));
        mx1 = fmaxf(mx1, __shfl_xor_sync(0xffffffffu, mx1, 2));
        const float mn0 = fmaxf(m0, mx0), mn1 = fmaxf(m1, mx1);
        const float cr0 = __expf(m0 - mn0), cr1 = __expf(m1 - mn1);
        l0 *= cr0; l1 *= cr1; m0 = mn0; m1 = mn1;
#pragma unroll
        for (int nt = 0; nt < 16; nt++) {
            oacc[nt][0] *= cr0; oacc[nt][1] *= cr0;
            oacc[nt][2] *= cr1; oacc[nt][3] *= cr1;
        }
        float ps0 = 0.f, ps1 = 0.f;
#pragma unroll
        for (int kb = 0; kb < 8; kb++) {
            const float p00 = __expf(sacc[2*kb][0]   - mn0), p01 = __expf(sacc[2*kb][1]   - mn0);
            const float p02 = __expf(sacc[2*kb][2]   - mn1), p03 = __expf(sacc[2*kb][3]   - mn1);
            const float p10 = __expf(sacc[2*kb+1][0] - mn0), p11 = __expf(sacc[2*kb+1][1] - mn0);
            const float p12 = __expf(sacc[2*kb+1][2] - mn1), p13 = __expf(sacc[2*kb+1][3] - mn1);
            pfrag[kb][0] = packh2(p00, p01);
            pfrag[kb][1] = packh2(p02, p03);
            pfrag[kb][2] = packh2(p10, p11);
            pfrag[kb][3] = packh2(p12, p13);
            ps0 += p00 + p01 + p10 + p11;
            ps1 += p02 + p03 + p12 + p13;
        }
        ps0 += __shfl_xor_sync(0xffffffffu, ps0, 1);
        ps0 += __shfl_xor_sync(0xffffffffu, ps0, 2);
        ps1 += __shfl_xor_sync(0xffffffffu, ps1, 1);
        ps1 += __shfl_xor_sync(0xffffffffu, ps1, 2);
        l0 += ps0; l1 += ps1;

        if (j + 1 < nkt) { CP_WAIT(1); } else { CP_WAIT(0); }
        __syncthreads();

#pragma unroll
        for (int kb = 0; kb < 8; kb++) {
            const int chunk = kb >> 2;
            const int g = (kb & 3) * 2 + (lane >> 4);
#pragma unroll
            for (int np = 0; np < 8; np++) {
                const int br = np * 16 + lr;
                const uint32_t boff = br * 128 + ((g ^ (br & 7)) << 4);
                uint32_t t4[4];
                LDSM_X4(t4, VS + chunk * 16384 + boff);
                uint32_t b0[2] = { t4[0], t4[2] };
                uint32_t b1[2] = { t4[1], t4[3] };
                mma16816_fp(oacc[2*np],   pfrag[kb], b0);
                mma16816_fp(oacc[2*np+1], pfrag[kb], b1);
            }
        }
        __syncthreads();
        if (j + 1 < nkt) { loadV(j + 1); CP_COMMIT(); }
    }

    // ---- writeout: fp16 AO ----
    const float inv0 = 1.f / l0, inv1 = 1.f / l1;
    const int bb = bh >> 4, hh = bh & 15;
    const int rgg0 = qb * 128 + wid * 16 + rloc;
    const size_t base0 = ((size_t)(bb * 2048 + rgg0)) * 2048 + hh * 128;
    const size_t base1 = base0 + (size_t)8 * 2048;
#pragma unroll
    for (int nt = 0; nt < 16; nt++) {
        const int d = nt * 8 + colloc;
        *(__half2*)(g_AOfh + base0 + d) = __floats2half2_rn(oacc[nt][0] * inv0, oacc[nt][1] * inv0);
        *(__half2*)(g_AOfh + base1 + d) = __floats2half2_rn(oacc[nt][2] * inv1, oacc[nt][3] * inv1);
    }
}

// ---------------- launch ----------------
extern "C" void kernel_launch(void* const* d_in, const int* in_sizes, int n_in,
                              void* d_out, int out_size)
{
    (void)in_sizes; (void)n_in; (void)out_size;
    const float* hidden = (const float*)d_in[0];
    const float* q_w = (const float*)d_in[2];
    const float* k_w = (const float*)d_in[3];
    const float* v_w = (const float*)d_in[4];
    const float* o_w = (const float*)d_in[5];
    float* out = (float*)d_out;

    cudaFuncSetAttribute(gemm_mma<1>, cudaFuncAttributeMaxDynamicSharedMemorySize, GT_SMEM);
    cudaFuncSetAttribute(gemm_mma<0>, cudaFuncAttributeMaxDynamicSharedMemorySize, GT_SMEM);
    cudaFuncSetAttribute(flash_mma, cudaFuncAttributeMaxDynamicSharedMemorySize, FL_SMEM);

    convert_all<<<dim3(8192, 5), 256>>>(hidden, q_w, k_w, v_w, o_w);
    gemm_mma<1><<<dim3(48, 32), 256, GT_SMEM>>>(nullptr);
    abar_cam<<<32, 256>>>();
    vt_update<<<4096, 256>>>();
    flash_mma<<<dim3(16, 32), 256, FL_SMEM>>>();
    gemm_mma<0><<<dim3(16, 32), 256, GT_SMEM>>>(out);
}